// round 1
// baseline (speedup 1.0000x reference)
#include <cuda_runtime.h>
#include <cstddef>

// ---------------------------------------------------------------------------
// Sinkhorn divergence (geomloss-style, p=2, blur=0.05, scaling=0.5, diam=32)
// N = M = 8192, D = 64.
// Strategy: precompute 4 cost matrices (C_xy, C_yx=C_xy^T, C_xx, C_yy) in fp32
// once (3 SIMT GEMMs + 1 transpose), then run 52 memory-bound streaming
// row-logsumexp ("softmin") passes + tiny vector-update kernels.
// ---------------------------------------------------------------------------

#define NPTS 8192
#define DIMS 64
#define NN   ((size_t)NPTS * (size_t)NPTS)   // 67108864 elements per matrix

// Scratch: 4 cost matrices + 11 small vectors, all in one device global.
// (cudaMalloc is forbidden; __device__ globals are the sanctioned scratch.)
#define VEC_COUNT 11
__device__ __align__(256) float d_buf[4 * NN + (size_t)VEC_COUNT * NPTS];

// vector slot indices within d_buf[4*NN + slot*NPTS]
#define V_HX   0
#define V_HY   1
#define V_ZERO 2   // never written: stays zero from BSS init
#define V_FAA  3
#define V_GBB  4
#define V_GAB  5
#define V_FBA  6
#define V_FT   7
#define V_GT   8
#define V_FS   9
#define V_GS   10

#define LOG2E_F 1.4426950408889634f
#define LN2_F   0.6931471805599453f
#define NEG_LOG_N_F (-9.010913347279288f)   // -ln(8192) = a_log = b_log

__device__ __forceinline__ float ex2_fast(float x) {
    float r; asm("ex2.approx.ftz.f32 %0, %1;" : "=f"(r) : "f"(x)); return r;
}
__device__ __forceinline__ float lg2_fast(float x) {
    float r; asm("lg2.approx.f32 %0, %1;" : "=f"(r) : "f"(x)); return r;
}

// ---------------------------------------------------------------------------
// half squared norms: h[i] = 0.5 * ||X_i||^2, one warp per row
// ---------------------------------------------------------------------------
__global__ void halfnorm_kernel(const float* __restrict__ X, float* __restrict__ h) {
    int warp = (blockIdx.x * blockDim.x + threadIdx.x) >> 5;
    int lane = threadIdx.x & 31;
    if (warp >= NPTS) return;
    float v0 = X[(size_t)warp * DIMS + lane];
    float v1 = X[(size_t)warp * DIMS + 32 + lane];
    float s = v0 * v0 + v1 * v1;
    #pragma unroll
    for (int o = 16; o > 0; o >>= 1) s += __shfl_xor_sync(0xffffffffu, s, o);
    if (lane == 0) h[warp] = 0.5f * s;
}

// ---------------------------------------------------------------------------
// C[i,j] = max(ha[i] + hb[j] - dot(A_i, B_j), 0)
// 128x128 tile per block, 256 threads, 8x8 per thread, K=64 in two 32-chunks.
// ---------------------------------------------------------------------------
__global__ void __launch_bounds__(256)
gemm_cost_kernel(const float* __restrict__ A, const float* __restrict__ B,
                 const float* __restrict__ ha, const float* __restrict__ hb,
                 float* __restrict__ C) {
    __shared__ float As[32][132];
    __shared__ float Bs[32][132];

    const int i0 = blockIdx.y * 128;
    const int j0 = blockIdx.x * 128;
    const int tid = threadIdx.x;
    const int tx = tid & 15;       // 0..15
    const int ty = tid >> 4;       // 0..15

    float acc[8][8];
    #pragma unroll
    for (int p = 0; p < 8; p++)
        #pragma unroll
        for (int q = 0; q < 8; q++) acc[p][q] = 0.0f;

    #pragma unroll
    for (int kc = 0; kc < 2; kc++) {
        // load 128 rows x 32 cols of A and B (transposed into shared)
        #pragma unroll
        for (int r = 0; r < 4; r++) {
            int idx = tid + 256 * r;          // 0..1023
            int row = idx >> 3;               // 0..127
            int c4  = idx & 7;                // 0..7 (float4 within 32 cols)
            float4 av = *(const float4*)(A + (size_t)(i0 + row) * DIMS + kc * 32 + c4 * 4);
            float4 bv = *(const float4*)(B + (size_t)(j0 + row) * DIMS + kc * 32 + c4 * 4);
            As[c4 * 4 + 0][row] = av.x; As[c4 * 4 + 1][row] = av.y;
            As[c4 * 4 + 2][row] = av.z; As[c4 * 4 + 3][row] = av.w;
            Bs[c4 * 4 + 0][row] = bv.x; Bs[c4 * 4 + 1][row] = bv.y;
            Bs[c4 * 4 + 2][row] = bv.z; Bs[c4 * 4 + 3][row] = bv.w;
        }
        __syncthreads();

        #pragma unroll 8
        for (int k = 0; k < 32; k++) {
            float a[8], b[8];
            *(float4*)&a[0] = *(const float4*)&As[k][ty * 8];
            *(float4*)&a[4] = *(const float4*)&As[k][ty * 8 + 4];
            *(float4*)&b[0] = *(const float4*)&Bs[k][tx * 8];
            *(float4*)&b[4] = *(const float4*)&Bs[k][tx * 8 + 4];
            #pragma unroll
            for (int p = 0; p < 8; p++)
                #pragma unroll
                for (int q = 0; q < 8; q++)
                    acc[p][q] = fmaf(a[p], b[q], acc[p][q]);
        }
        __syncthreads();
    }

    // epilogue: C = max(ha + hb - dot, 0)
    float hbv[8];
    #pragma unroll
    for (int q = 0; q < 8; q++) hbv[q] = hb[j0 + tx * 8 + q];
    #pragma unroll
    for (int p = 0; p < 8; p++) {
        int i = i0 + ty * 8 + p;
        float hai = ha[i];
        float4 o0, o1;
        o0.x = fmaxf(hai + hbv[0] - acc[p][0], 0.0f);
        o0.y = fmaxf(hai + hbv[1] - acc[p][1], 0.0f);
        o0.z = fmaxf(hai + hbv[2] - acc[p][2], 0.0f);
        o0.w = fmaxf(hai + hbv[3] - acc[p][3], 0.0f);
        o1.x = fmaxf(hai + hbv[4] - acc[p][4], 0.0f);
        o1.y = fmaxf(hai + hbv[5] - acc[p][5], 0.0f);
        o1.z = fmaxf(hai + hbv[6] - acc[p][6], 0.0f);
        o1.w = fmaxf(hai + hbv[7] - acc[p][7], 0.0f);
        float* cp = C + (size_t)i * NPTS + j0 + tx * 8;
        *(float4*)cp       = o0;
        *(float4*)(cp + 4) = o1;
    }
}

// ---------------------------------------------------------------------------
// out[j,i] = in[i,j]  (32x32 tiles through shared)
// ---------------------------------------------------------------------------
__global__ void transpose_kernel(const float* __restrict__ in, float* __restrict__ out) {
    __shared__ float tile[32][33];
    int bx = blockIdx.x * 32, by = blockIdx.y * 32;
    int tx = threadIdx.x, ty = threadIdx.y;   // block (32, 8)
    #pragma unroll
    for (int r = 0; r < 32; r += 8)
        tile[ty + r][tx] = in[(size_t)(by + ty + r) * NPTS + bx + tx];
    __syncthreads();
    #pragma unroll
    for (int r = 0; r < 32; r += 8)
        out[(size_t)(bx + ty + r) * NPTS + by + tx] = tile[tx][ty + r];
}

// ---------------------------------------------------------------------------
// softmin over row of C with h_log[j] = NEG_LOG_N + g[j]*inv_eps:
//   out[row] = -eps * logsumexp_j( NEG_LOG_N + (g[j] - C[row,j]) * inv_eps )
// 1 block per row; 256 threads x 32 elements in registers; exp2 domain.
// ---------------------------------------------------------------------------
__global__ void __launch_bounds__(256)
softmin_kernel(const float* __restrict__ C, const float* __restrict__ g,
               float inv_eps, float eps, float* __restrict__ out) {
    const int row = blockIdx.x;
    const int tid = threadIdx.x;
    const float4* __restrict__ Crow = (const float4*)(C + (size_t)row * NPTS);
    const float4* __restrict__ G    = (const float4*)g;

    const float k1 = inv_eps * LOG2E_F;
    const float k2 = NEG_LOG_N_F * LOG2E_F;

    float t[32];
    #pragma unroll
    for (int u = 0; u < 8; u++) {
        int idx = tid + 256 * u;
        float4 c4 = Crow[idx];
        float4 g4 = G[idx];
        t[4 * u + 0] = fmaf(g4.x - c4.x, k1, k2);
        t[4 * u + 1] = fmaf(g4.y - c4.y, k1, k2);
        t[4 * u + 2] = fmaf(g4.z - c4.z, k1, k2);
        t[4 * u + 3] = fmaf(g4.w - c4.w, k1, k2);
    }

    float m = t[0];
    #pragma unroll
    for (int i = 1; i < 32; i++) m = fmaxf(m, t[i]);
    float s = 0.0f;
    #pragma unroll
    for (int i = 0; i < 32; i++) s += ex2_fast(t[i] - m);

    __shared__ float red[256];
    red[tid] = m;
    __syncthreads();
    #pragma unroll
    for (int o = 128; o > 0; o >>= 1) {
        if (tid < o) red[tid] = fmaxf(red[tid], red[tid + o]);
        __syncthreads();
    }
    float M = red[0];
    __syncthreads();

    red[tid] = s * ex2_fast(m - M);
    __syncthreads();
    #pragma unroll
    for (int o = 128; o > 0; o >>= 1) {
        if (tid < o) red[tid] += red[tid + o];
        __syncthreads();
    }
    if (tid == 0)
        out[row] = -eps * LN2_F * (M + lg2_fast(red[0]));
}

// ---------------------------------------------------------------------------
// symmetric averaged updates: v = 0.5*(v + vt) for the 4 potentials
// ---------------------------------------------------------------------------
__global__ void update_kernel(float* __restrict__ fba, const float* __restrict__ ft,
                              float* __restrict__ gab, const float* __restrict__ gt,
                              float* __restrict__ faa, const float* __restrict__ fs,
                              float* __restrict__ gbb, const float* __restrict__ gs) {
    int i = blockIdx.x * blockDim.x + threadIdx.x;
    if (i < NPTS) {
        fba[i] = 0.5f * (fba[i] + ft[i]);
        gab[i] = 0.5f * (gab[i] + gt[i]);
        faa[i] = 0.5f * (faa[i] + fs[i]);
        gbb[i] = 0.5f * (gbb[i] + gs[i]);
    }
}

// ---------------------------------------------------------------------------
// out = mean(fbf - faf) + mean(gaf - gbf)
// ---------------------------------------------------------------------------
__global__ void final_kernel(const float* __restrict__ fbf, const float* __restrict__ faf,
                             const float* __restrict__ gaf, const float* __restrict__ gbf,
                             float* __restrict__ out) {
    __shared__ float sh[256];
    float s = 0.0f;
    for (int i = threadIdx.x; i < NPTS; i += 256)
        s += (fbf[i] - faf[i]) + (gaf[i] - gbf[i]);
    sh[threadIdx.x] = s;
    __syncthreads();
    #pragma unroll
    for (int o = 128; o > 0; o >>= 1) {
        if (threadIdx.x < o) sh[threadIdx.x] += sh[threadIdx.x + o];
        __syncthreads();
    }
    if (threadIdx.x == 0) out[0] = sh[0] * (1.0f / (float)NPTS);
}

// ---------------------------------------------------------------------------
// host orchestration
// ---------------------------------------------------------------------------
extern "C" void kernel_launch(void* const* d_in, const int* in_sizes, int n_in,
                              void* d_out, int out_size) {
    (void)in_sizes; (void)n_in; (void)out_size;
    const float* x = (const float*)d_in[0];   // pred_signature  [8192,64]
    const float* y = (const float*)d_in[1];   // target_signature[8192,64]
    float* out = (float*)d_out;

    float* buf = nullptr;
    cudaGetSymbolAddress((void**)&buf, d_buf);

    float* Cxy = buf;
    float* Cyx = buf + NN;
    float* Cxx = buf + 2 * NN;
    float* Cyy = buf + 3 * NN;
    float* vec = buf + 4 * NN;
    float* hx   = vec + (size_t)V_HX   * NPTS;
    float* hy   = vec + (size_t)V_HY   * NPTS;
    float* zero = vec + (size_t)V_ZERO * NPTS;
    float* faa  = vec + (size_t)V_FAA  * NPTS;
    float* gbb  = vec + (size_t)V_GBB  * NPTS;
    float* gab  = vec + (size_t)V_GAB  * NPTS;
    float* fba  = vec + (size_t)V_FBA  * NPTS;
    float* ft   = vec + (size_t)V_FT   * NPTS;
    float* gt   = vec + (size_t)V_GT   * NPTS;
    float* fs   = vec + (size_t)V_FS   * NPTS;
    float* gs   = vec + (size_t)V_GS   * NPTS;

    // geomloss epsilon schedule for diameter=32, blur=0.05, scaling=0.5, p=2
    static const float EPS[11] = {1024.0f, 256.0f, 64.0f, 16.0f, 4.0f, 1.0f,
                                  0.25f, 0.0625f, 0.015625f, 0.00390625f, 0.0025f};

    halfnorm_kernel<<<1024, 256>>>(x, hx);
    halfnorm_kernel<<<1024, 256>>>(y, hy);

    dim3 gg(64, 64);
    gemm_cost_kernel<<<gg, 256>>>(x, y, hx, hy, Cxy);
    gemm_cost_kernel<<<gg, 256>>>(x, x, hx, hx, Cxx);
    gemm_cost_kernel<<<gg, 256>>>(y, y, hy, hy, Cyy);
    transpose_kernel<<<dim3(256, 256), dim3(32, 8)>>>(Cxy, Cyx);

    // init potentials at eps0 (h_log = a_log / b_log only -> g = zeros)
    {
        float e0 = EPS[0], ie0 = 1.0f / e0;
        softmin_kernel<<<NPTS, 256>>>(Cxx, zero, ie0, e0, faa);
        softmin_kernel<<<NPTS, 256>>>(Cyy, zero, ie0, e0, gbb);
        softmin_kernel<<<NPTS, 256>>>(Cyx, zero, ie0, e0, gab);
        softmin_kernel<<<NPTS, 256>>>(Cxy, zero, ie0, e0, fba);
    }

    // epsilon-scaling loop with symmetric averaged updates
    for (int it = 0; it < 11; it++) {
        float e = EPS[it], ie = 1.0f / e;
        softmin_kernel<<<NPTS, 256>>>(Cxy, gab, ie, e, ft);
        softmin_kernel<<<NPTS, 256>>>(Cyx, fba, ie, e, gt);
        softmin_kernel<<<NPTS, 256>>>(Cxx, faa, ie, e, fs);
        softmin_kernel<<<NPTS, 256>>>(Cyy, gbb, ie, e, gs);
        update_kernel<<<32, 256>>>(fba, ft, gab, gt, faa, fs, gbb, gs);
    }

    // final non-averaged extrapolation at eps = blur^p
    {
        float ef = EPS[10], ief = 1.0f / ef;
        softmin_kernel<<<NPTS, 256>>>(Cxy, gab, ief, ef, ft);   // f_ba_f
        softmin_kernel<<<NPTS, 256>>>(Cyx, fba, ief, ef, gt);   // g_ab_f
        softmin_kernel<<<NPTS, 256>>>(Cxx, faa, ief, ef, fs);   // f_aa_f
        softmin_kernel<<<NPTS, 256>>>(Cyy, gbb, ief, ef, gs);   // g_bb_f
    }

    final_kernel<<<1, 256>>>(ft, fs, gt, gs, out);
}

// round 2
// speedup vs baseline: 1.4264x; 1.4264x over previous
#include <cuda_runtime.h>
#include <cstddef>

// ---------------------------------------------------------------------------
// Sinkhorn divergence (geomloss p=2, blur=0.05, scaling=0.5, diameter=32)
// N = M = 8192, D = 64.
// R2: cost matrices stored as uint16 fixed-point (C*128), halving streaming
// traffic; GEMM bank-conflict fix + symmetric-tile exploitation + fused
// transposed write (no separate transpose kernel).
// ---------------------------------------------------------------------------

#define NPTS 8192
#define DIMS 64
#define NN   ((size_t)NPTS * (size_t)NPTS)

#define QSCALE 128.0f
#define QINV   (1.0f / 128.0f)

// Scratch (cudaMalloc forbidden): 4 quantized matrices (512 MB) + vectors.
__device__ __align__(256) unsigned short d_cq[4 * NN];
__device__ __align__(256) float d_vecbuf[11 * NPTS];

#define V_HX   0
#define V_HY   1
#define V_ZERO 2   // never written: zero from BSS init
#define V_FAA  3
#define V_GBB  4
#define V_GAB  5
#define V_FBA  6
#define V_FT   7
#define V_GT   8
#define V_FS   9
#define V_GS   10

#define LOG2E_F 1.4426950408889634f
#define LN2_F   0.6931471805599453f
#define NEG_LOG_N_F (-9.010913347279288f)   // -ln(8192)

__device__ __forceinline__ float ex2_fast(float x) {
    float r; asm("ex2.approx.ftz.f32 %0, %1;" : "=f"(r) : "f"(x)); return r;
}
__device__ __forceinline__ float lg2_fast(float x) {
    float r; asm("lg2.approx.f32 %0, %1;" : "=f"(r) : "f"(x)); return r;
}
// exact u16 -> float via 2^23 magic (PRMT + FADD)
__device__ __forceinline__ float dec_lo(unsigned w) {
    return __uint_as_float(__byte_perm(w, 0x4B000000u, 0x7410)) - 8388608.0f;
}
__device__ __forceinline__ float dec_hi(unsigned w) {
    return __uint_as_float(__byte_perm(w, 0x4B000000u, 0x7432)) - 8388608.0f;
}

// ---------------------------------------------------------------------------
// h[i] = 0.5 * ||X_i||^2, one warp per row
// ---------------------------------------------------------------------------
__global__ void halfnorm_kernel(const float* __restrict__ X, float* __restrict__ h) {
    int warp = (blockIdx.x * blockDim.x + threadIdx.x) >> 5;
    int lane = threadIdx.x & 31;
    if (warp >= NPTS) return;
    float v0 = X[(size_t)warp * DIMS + lane];
    float v1 = X[(size_t)warp * DIMS + 32 + lane];
    float s = v0 * v0 + v1 * v1;
    #pragma unroll
    for (int o = 16; o > 0; o >>= 1) s += __shfl_xor_sync(0xffffffffu, s, o);
    if (lane == 0) h[warp] = 0.5f * s;
}

// ---------------------------------------------------------------------------
// C[i,j] = quant( max(ha[i] + hb[j] - dot(A_i,B_j), 0) ), uint16, scale 128.
// Writes direct tile to C and transposed tile to CT (via swizzled smem).
// symmetric=1: skip lower-triangle blocks (CT==C gives the mirror).
// 128x128 tile per block, 256 threads, 8x8 per thread, K in two 32-chunks.
// ---------------------------------------------------------------------------
__global__ void __launch_bounds__(256)
gemm_cost_q(const float* __restrict__ A, const float* __restrict__ B,
            const float* __restrict__ ha, const float* __restrict__ hb,
            unsigned short* __restrict__ C, unsigned short* __restrict__ CT,
            int symmetric) {
    int bi = blockIdx.y, bj = blockIdx.x;
    if (symmetric && bi > bj) return;
    const int i0 = bi * 128, j0 = bj * 128;

    // union: two 32x132 float stages (33792 B) / 128x136 u16 mirror tile (34816 B)
    __shared__ __align__(16) unsigned char smem_raw[34816];
    float (*As)[132] = (float (*)[132])smem_raw;
    float (*Bs)[132] = (float (*)[132])(smem_raw + 32 * 132 * 4 / 2 * 0 + 16896);

    const int tid  = threadIdx.x;
    const int lane = tid & 31, warp = tid >> 5;
    const int wy = warp >> 1, wx = warp & 1;
    const int ty2 = lane & 3, tx2 = lane >> 2;     // a-frags: banks 0/8/16/24
    const int r0 = wy * 32 + ty2 * 8;
    const int c0 = wx * 64 + tx2 * 8;

    float acc[8][8];
    #pragma unroll
    for (int p = 0; p < 8; p++)
        #pragma unroll
        for (int q = 0; q < 8; q++) acc[p][q] = 0.0f;

    #pragma unroll
    for (int kc = 0; kc < 2; kc++) {
        #pragma unroll
        for (int u = 0; u < 4; u++) {
            int idx = tid + 256 * u;          // 0..1023
            int row = idx >> 3;               // 0..127
            int kq  = idx & 7;                // float4 within 32 k's
            float4 av = *(const float4*)(A + (size_t)(i0 + row) * DIMS + kc * 32 + kq * 4);
            float4 bv = *(const float4*)(B + (size_t)(j0 + row) * DIMS + kc * 32 + kq * 4);
            As[kq * 4 + 0][row] = av.x; As[kq * 4 + 1][row] = av.y;
            As[kq * 4 + 2][row] = av.z; As[kq * 4 + 3][row] = av.w;
            Bs[kq * 4 + 0][row] = bv.x; Bs[kq * 4 + 1][row] = bv.y;
            Bs[kq * 4 + 2][row] = bv.z; Bs[kq * 4 + 3][row] = bv.w;
        }
        __syncthreads();

        #pragma unroll 4
        for (int k = 0; k < 32; k++) {
            float a[8], b[8];
            *(float4*)&a[0] = *(const float4*)&As[k][r0];
            *(float4*)&a[4] = *(const float4*)&As[k][r0 + 4];
            *(float4*)&b[0] = *(const float4*)&Bs[k][c0];
            *(float4*)&b[4] = *(const float4*)&Bs[k][c0 + 4];
            #pragma unroll
            for (int p = 0; p < 8; p++)
                #pragma unroll
                for (int q = 0; q < 8; q++)
                    acc[p][q] = fmaf(a[p], b[q], acc[p][q]);
        }
        __syncthreads();
    }

    float hav[8], hbv[8];
    #pragma unroll
    for (int p = 0; p < 8; p++) hav[p] = ha[i0 + r0 + p];
    #pragma unroll
    for (int q = 0; q < 8; q++) hbv[q] = hb[j0 + c0 + q];

    // ---- direct tile store (row-major packing) ----
    #pragma unroll
    for (int p = 0; p < 8; p++) {
        unsigned v[8];
        #pragma unroll
        for (int q = 0; q < 8; q++) {
            float val = fmaxf(hav[p] + hbv[q] - acc[p][q], 0.0f) * QSCALE;
            unsigned x = __float2uint_rn(val);
            v[q] = x > 65535u ? 65535u : x;
        }
        uint4 w;
        w.x = v[0] | (v[1] << 16); w.y = v[2] | (v[3] << 16);
        w.z = v[4] | (v[5] << 16); w.w = v[6] | (v[7] << 16);
        *(uint4*)(C + (size_t)(i0 + r0 + p) * NPTS + j0 + c0) = w;
    }

    // ---- transposed tile via swizzled shared u16 staging ----
    __syncthreads();
    unsigned short* sh = (unsigned short*)smem_raw;
    #pragma unroll
    for (int q = 0; q < 8; q++) {
        int c = c0 + q;
        unsigned v[8];
        #pragma unroll
        for (int p = 0; p < 8; p++) {
            float val = fmaxf(hav[p] + hbv[q] - acc[p][q], 0.0f) * QSCALE;
            unsigned x = __float2uint_rn(val);
            v[p] = x > 65535u ? 65535u : x;
        }
        uint4 w;
        w.x = v[0] | (v[1] << 16); w.y = v[2] | (v[3] << 16);
        w.z = v[4] | (v[5] << 16); w.w = v[6] | (v[7] << 16);
        int sw = r0 ^ (((c >> 3) & 7) << 3);
        *(uint4*)&sh[c * 136 + sw] = w;
    }
    __syncthreads();
    #pragma unroll
    for (int u = 0; u < 8; u++) {
        int idx = tid + 256 * u;     // 0..2047
        int cl = idx >> 4;           // 0..127 (local column = output row)
        int rq = idx & 15;           // uint4 index within 128 rows
        int sw = (rq * 8) ^ (((cl >> 3) & 7) << 3);
        uint4 w = *(const uint4*)&sh[cl * 136 + sw];
        *(uint4*)(CT + (size_t)(j0 + cl) * NPTS + i0 + rq * 8) = w;
    }
}

// ---------------------------------------------------------------------------
// softmin over row of quantized C:
//   out[row] = -eps * LSE_j( -ln(N) + (g[j] - Cq[row,j]/128) / eps )   (exp2 domain)
// 1 block/row, 256 threads x 32 elements (4x uint4 = 8 u16 each).
// ---------------------------------------------------------------------------
__global__ void __launch_bounds__(256)
softmin_q(const unsigned short* __restrict__ Cq, const float* __restrict__ g,
          float inv_eps, float eps, float* __restrict__ out) {
    const int row = blockIdx.x;
    const int tid = threadIdx.x;
    const uint4* __restrict__ Crow = (const uint4*)(Cq + (size_t)row * NPTS);
    const float4* __restrict__ G   = (const float4*)g;

    const float k1 = inv_eps * LOG2E_F;
    const float kq = -k1 * QINV;
    const float kb = NEG_LOG_N_F * LOG2E_F;

    float t[32];
    #pragma unroll
    for (int u = 0; u < 4; u++) {
        int idx = tid + 256 * u;
        uint4 w = Crow[idx];
        float4 ga = G[2 * idx];
        float4 gb = G[2 * idx + 1];
        t[8*u + 0] = fmaf(dec_lo(w.x), kq, fmaf(ga.x, k1, kb));
        t[8*u + 1] = fmaf(dec_hi(w.x), kq, fmaf(ga.y, k1, kb));
        t[8*u + 2] = fmaf(dec_lo(w.y), kq, fmaf(ga.z, k1, kb));
        t[8*u + 3] = fmaf(dec_hi(w.y), kq, fmaf(ga.w, k1, kb));
        t[8*u + 4] = fmaf(dec_lo(w.z), kq, fmaf(gb.x, k1, kb));
        t[8*u + 5] = fmaf(dec_hi(w.z), kq, fmaf(gb.y, k1, kb));
        t[8*u + 6] = fmaf(dec_lo(w.w), kq, fmaf(gb.z, k1, kb));
        t[8*u + 7] = fmaf(dec_hi(w.w), kq, fmaf(gb.w, k1, kb));
    }

    float m = t[0];
    #pragma unroll
    for (int i = 1; i < 32; i++) m = fmaxf(m, t[i]);
    float s = 0.0f;
    #pragma unroll
    for (int i = 0; i < 32; i++) s += ex2_fast(t[i] - m);

    __shared__ float red[256];
    red[tid] = m;
    __syncthreads();
    #pragma unroll
    for (int o = 128; o > 0; o >>= 1) {
        if (tid < o) red[tid] = fmaxf(red[tid], red[tid + o]);
        __syncthreads();
    }
    float M = red[0];
    __syncthreads();

    red[tid] = s * ex2_fast(m - M);
    __syncthreads();
    #pragma unroll
    for (int o = 128; o > 0; o >>= 1) {
        if (tid < o) red[tid] += red[tid + o];
        __syncthreads();
    }
    if (tid == 0)
        out[row] = -eps * LN2_F * (M + lg2_fast(red[0]));
}

// ---------------------------------------------------------------------------
// v = 0.5*(v + vt) for the 4 potentials
// ---------------------------------------------------------------------------
__global__ void update_kernel(float* __restrict__ fba, const float* __restrict__ ft,
                              float* __restrict__ gab, const float* __restrict__ gt,
                              float* __restrict__ faa, const float* __restrict__ fs,
                              float* __restrict__ gbb, const float* __restrict__ gs) {
    int i = blockIdx.x * blockDim.x + threadIdx.x;
    if (i < NPTS) {
        fba[i] = 0.5f * (fba[i] + ft[i]);
        gab[i] = 0.5f * (gab[i] + gt[i]);
        faa[i] = 0.5f * (faa[i] + fs[i]);
        gbb[i] = 0.5f * (gbb[i] + gs[i]);
    }
}

__global__ void final_kernel(const float* __restrict__ fbf, const float* __restrict__ faf,
                             const float* __restrict__ gaf, const float* __restrict__ gbf,
                             float* __restrict__ out) {
    __shared__ float sh[256];
    float s = 0.0f;
    for (int i = threadIdx.x; i < NPTS; i += 256)
        s += (fbf[i] - faf[i]) + (gaf[i] - gbf[i]);
    sh[threadIdx.x] = s;
    __syncthreads();
    #pragma unroll
    for (int o = 128; o > 0; o >>= 1) {
        if (threadIdx.x < o) sh[threadIdx.x] += sh[threadIdx.x + o];
        __syncthreads();
    }
    if (threadIdx.x == 0) out[0] = sh[0] * (1.0f / (float)NPTS);
}

// ---------------------------------------------------------------------------
// host orchestration
// ---------------------------------------------------------------------------
extern "C" void kernel_launch(void* const* d_in, const int* in_sizes, int n_in,
                              void* d_out, int out_size) {
    (void)in_sizes; (void)n_in; (void)out_size;
    const float* x = (const float*)d_in[0];
    const float* y = (const float*)d_in[1];
    float* out = (float*)d_out;

    unsigned short* cq = nullptr;
    float* vec = nullptr;
    cudaGetSymbolAddress((void**)&cq, d_cq);
    cudaGetSymbolAddress((void**)&vec, d_vecbuf);

    unsigned short* Cxy = cq;
    unsigned short* Cyx = cq + NN;
    unsigned short* Cxx = cq + 2 * NN;
    unsigned short* Cyy = cq + 3 * NN;
    float* hx   = vec + (size_t)V_HX   * NPTS;
    float* hy   = vec + (size_t)V_HY   * NPTS;
    float* zero = vec + (size_t)V_ZERO * NPTS;
    float* faa  = vec + (size_t)V_FAA  * NPTS;
    float* gbb  = vec + (size_t)V_GBB  * NPTS;
    float* gab  = vec + (size_t)V_GAB  * NPTS;
    float* fba  = vec + (size_t)V_FBA  * NPTS;
    float* ft   = vec + (size_t)V_FT   * NPTS;
    float* gt   = vec + (size_t)V_GT   * NPTS;
    float* fs   = vec + (size_t)V_FS   * NPTS;
    float* gs   = vec + (size_t)V_GS   * NPTS;

    static const float EPS[11] = {1024.0f, 256.0f, 64.0f, 16.0f, 4.0f, 1.0f,
                                  0.25f, 0.0625f, 0.015625f, 0.00390625f, 0.0025f};

    halfnorm_kernel<<<1024, 256>>>(x, hx);
    halfnorm_kernel<<<1024, 256>>>(y, hy);

    dim3 gg(64, 64);
    gemm_cost_q<<<gg, 256>>>(x, y, hx, hy, Cxy, Cyx, 0);
    gemm_cost_q<<<gg, 256>>>(x, x, hx, hx, Cxx, Cxx, 1);
    gemm_cost_q<<<gg, 256>>>(y, y, hy, hy, Cyy, Cyy, 1);

    {   // init potentials at eps0 (g = zeros -> h_log = log-weights only)
        float e0 = EPS[0], ie0 = 1.0f / e0;
        softmin_q<<<NPTS, 256>>>(Cxx, zero, ie0, e0, faa);
        softmin_q<<<NPTS, 256>>>(Cyy, zero, ie0, e0, gbb);
        softmin_q<<<NPTS, 256>>>(Cyx, zero, ie0, e0, gab);
        softmin_q<<<NPTS, 256>>>(Cxy, zero, ie0, e0, fba);
    }

    for (int it = 0; it < 11; it++) {
        float e = EPS[it], ie = 1.0f / e;
        softmin_q<<<NPTS, 256>>>(Cxy, gab, ie, e, ft);
        softmin_q<<<NPTS, 256>>>(Cyx, fba, ie, e, gt);
        softmin_q<<<NPTS, 256>>>(Cxx, faa, ie, e, fs);
        softmin_q<<<NPTS, 256>>>(Cyy, gbb, ie, e, gs);
        update_kernel<<<32, 256>>>(fba, ft, gab, gt, faa, fs, gbb, gs);
    }

    {   // final non-averaged extrapolation at eps = blur^p
        float ef = EPS[10], ief = 1.0f / ef;
        softmin_q<<<NPTS, 256>>>(Cxy, gab, ief, ef, ft);   // f_ba_f
        softmin_q<<<NPTS, 256>>>(Cyx, fba, ief, ef, gt);   // g_ab_f
        softmin_q<<<NPTS, 256>>>(Cxx, faa, ief, ef, fs);   // f_aa_f
        softmin_q<<<NPTS, 256>>>(Cyy, gbb, ief, ef, gs);   // g_bb_f
    }

    final_kernel<<<1, 256>>>(ft, fs, gt, gs, out);
}

// round 3
// speedup vs baseline: 1.5864x; 1.1122x over previous
#include <cuda_runtime.h>
#include <cstddef>

// ---------------------------------------------------------------------------
// Sinkhorn divergence (geomloss p=2, blur=0.05, scaling=0.5, diameter=32)
// N = M = 8192, D = 64.
// R3: merged 4-in-1 softmin launches, warp-shuffle LSE reductions, and
// hierarchical chunk pruning (per-row per-128-col chunk mins computed in the
// GEMM epilogue; chunks provably below the row max by >30 bits are skipped).
// ---------------------------------------------------------------------------

#define NPTS 8192
#define DIMS 64
#define NN      ((size_t)NPTS * (size_t)NPTS)
#define NCHUNK  64                       // 8192 / 128
#define QSCALE  128.0f
#define QINV    (1.0f / 128.0f)

__device__ __align__(256) unsigned short d_cq[4 * NN];              // 512 MB
__device__ __align__(256) unsigned short d_cmin[4 * NPTS * NCHUNK]; // 4 MB
__device__ __align__(256) float d_gstat[2 * 4 * NCHUNK];            // min|max
__device__ __align__(256) float d_vecbuf[11 * NPTS];

#define V_HX   0
#define V_HY   1
#define V_ZERO 2   // never written: zero from BSS (serves as zero g AND zero gstats)
#define V_FAA  3
#define V_GBB  4
#define V_GAB  5
#define V_FBA  6
#define V_FT   7
#define V_GT   8
#define V_FS   9
#define V_GS   10

#define LOG2E_F 1.4426950408889634f
#define LN2_F   0.6931471805599453f
#define NEG_LOG_N_F (-9.010913347279288f)   // -ln(8192)
#define PRUNE_MARGIN 20.794415f             // 30 * ln2

__device__ __forceinline__ float ex2_fast(float x) {
    float r; asm("ex2.approx.ftz.f32 %0, %1;" : "=f"(r) : "f"(x)); return r;
}
__device__ __forceinline__ float lg2_fast(float x) {
    float r; asm("lg2.approx.f32 %0, %1;" : "=f"(r) : "f"(x)); return r;
}
__device__ __forceinline__ float dec_lo(unsigned w) {
    return __uint_as_float(__byte_perm(w, 0x4B000000u, 0x7410)) - 8388608.0f;
}
__device__ __forceinline__ float dec_hi(unsigned w) {
    return __uint_as_float(__byte_perm(w, 0x4B000000u, 0x7432)) - 8388608.0f;
}

// ---------------------------------------------------------------------------
__global__ void halfnorm_kernel(const float* __restrict__ X, float* __restrict__ h) {
    int warp = (blockIdx.x * blockDim.x + threadIdx.x) >> 5;
    int lane = threadIdx.x & 31;
    if (warp >= NPTS) return;
    float v0 = X[(size_t)warp * DIMS + lane];
    float v1 = X[(size_t)warp * DIMS + 32 + lane];
    float s = v0 * v0 + v1 * v1;
    #pragma unroll
    for (int o = 16; o > 0; o >>= 1) s += __shfl_xor_sync(0xffffffffu, s, o);
    if (lane == 0) h[warp] = 0.5f * s;
}

// ---------------------------------------------------------------------------
// C[i,j] = quant(max(ha[i]+hb[j]-dot,0)); writes tile + transposed tile + the
// per-row chunk mins for both orientations. symmetric=1 skips lower triangle.
// ---------------------------------------------------------------------------
__global__ void __launch_bounds__(256)
gemm_cost_q(const float* __restrict__ A, const float* __restrict__ B,
            const float* __restrict__ ha, const float* __restrict__ hb,
            unsigned short* __restrict__ C, unsigned short* __restrict__ CT,
            unsigned short* __restrict__ cminC, unsigned short* __restrict__ cminCT,
            int symmetric) {
    int bi = blockIdx.y, bj = blockIdx.x;
    if (symmetric && bi > bj) return;
    const int i0 = bi * 128, j0 = bj * 128;

    __shared__ __align__(16) unsigned char smem_raw[34816];  // stages / u16 mirror
    __shared__ unsigned sm_r[2][128];
    __shared__ unsigned sm_c[4][128];
    float (*As)[132] = (float (*)[132])smem_raw;
    float (*Bs)[132] = (float (*)[132])(smem_raw + 16896);

    const int tid  = threadIdx.x;
    const int lane = tid & 31, warp = tid >> 5;
    const int wy = warp >> 1, wx = warp & 1;
    const int ty2 = lane & 3, tx2 = lane >> 2;
    const int r0 = wy * 32 + ty2 * 8;
    const int c0 = wx * 64 + tx2 * 8;

    float acc[8][8];
    #pragma unroll
    for (int p = 0; p < 8; p++)
        #pragma unroll
        for (int q = 0; q < 8; q++) acc[p][q] = 0.0f;

    #pragma unroll
    for (int kc = 0; kc < 2; kc++) {
        #pragma unroll
        for (int u = 0; u < 4; u++) {
            int idx = tid + 256 * u;
            int row = idx >> 3;
            int kq  = idx & 7;
            float4 av = *(const float4*)(A + (size_t)(i0 + row) * DIMS + kc * 32 + kq * 4);
            float4 bv = *(const float4*)(B + (size_t)(j0 + row) * DIMS + kc * 32 + kq * 4);
            As[kq * 4 + 0][row] = av.x; As[kq * 4 + 1][row] = av.y;
            As[kq * 4 + 2][row] = av.z; As[kq * 4 + 3][row] = av.w;
            Bs[kq * 4 + 0][row] = bv.x; Bs[kq * 4 + 1][row] = bv.y;
            Bs[kq * 4 + 2][row] = bv.z; Bs[kq * 4 + 3][row] = bv.w;
        }
        __syncthreads();

        #pragma unroll 4
        for (int k = 0; k < 32; k++) {
            float a[8], b[8];
            *(float4*)&a[0] = *(const float4*)&As[k][r0];
            *(float4*)&a[4] = *(const float4*)&As[k][r0 + 4];
            *(float4*)&b[0] = *(const float4*)&Bs[k][c0];
            *(float4*)&b[4] = *(const float4*)&Bs[k][c0 + 4];
            #pragma unroll
            for (int p = 0; p < 8; p++)
                #pragma unroll
                for (int q = 0; q < 8; q++)
                    acc[p][q] = fmaf(a[p], b[q], acc[p][q]);
        }
        __syncthreads();
    }

    float hav[8], hbv[8];
    #pragma unroll
    for (int p = 0; p < 8; p++) hav[p] = ha[i0 + r0 + p];
    #pragma unroll
    for (int q = 0; q < 8; q++) hbv[q] = hb[j0 + c0 + q];

    // direct tile store + row/col mins of quantized values
    unsigned colq[8];
    #pragma unroll
    for (int q = 0; q < 8; q++) colq[q] = 0xFFFFu;
    unsigned rowq[8];
    #pragma unroll
    for (int p = 0; p < 8; p++) {
        unsigned v[8], rmin = 0xFFFFu;
        #pragma unroll
        for (int q = 0; q < 8; q++) {
            float val = fmaxf(hav[p] + hbv[q] - acc[p][q], 0.0f) * QSCALE;
            unsigned x = __float2uint_rn(val);
            v[q] = x > 65535u ? 65535u : x;
            rmin = min(rmin, v[q]);
            colq[q] = min(colq[q], v[q]);
        }
        rowq[p] = rmin;
        uint4 w;
        w.x = v[0] | (v[1] << 16); w.y = v[2] | (v[3] << 16);
        w.z = v[4] | (v[5] << 16); w.w = v[6] | (v[7] << 16);
        *(uint4*)(C + (size_t)(i0 + r0 + p) * NPTS + j0 + c0) = w;
    }

    // reduce row mins over tx2 (lane bits 2..4), store per-wx half
    #pragma unroll
    for (int p = 0; p < 8; p++) {
        unsigned r = rowq[p];
        r = min(r, __shfl_xor_sync(0xffffffffu, r, 4));
        r = min(r, __shfl_xor_sync(0xffffffffu, r, 8));
        r = min(r, __shfl_xor_sync(0xffffffffu, r, 16));
        if (tx2 == 0) sm_r[wx][r0 + p] = r;
    }
    // reduce col mins over ty2 (lane bits 0..1), store per-wy quarter
    #pragma unroll
    for (int q = 0; q < 8; q++) {
        unsigned c = colq[q];
        c = min(c, __shfl_xor_sync(0xffffffffu, c, 1));
        c = min(c, __shfl_xor_sync(0xffffffffu, c, 2));
        if (ty2 == 0) sm_c[wy][c0 + q] = c;
    }
    __syncthreads();
    if (tid < 128) {
        unsigned rm = min(sm_r[0][tid], sm_r[1][tid]);
        cminC[(size_t)(i0 + tid) * NCHUNK + bj] = (unsigned short)rm;
        unsigned cm = min(min(sm_c[0][tid], sm_c[1][tid]),
                          min(sm_c[2][tid], sm_c[3][tid]));
        cminCT[(size_t)(j0 + tid) * NCHUNK + bi] = (unsigned short)cm;
    }

    // transposed tile via swizzled shared u16 staging
    __syncthreads();
    unsigned short* sh = (unsigned short*)smem_raw;
    #pragma unroll
    for (int q = 0; q < 8; q++) {
        int c = c0 + q;
        unsigned v[8];
        #pragma unroll
        for (int p = 0; p < 8; p++) {
            float val = fmaxf(hav[p] + hbv[q] - acc[p][q], 0.0f) * QSCALE;
            unsigned x = __float2uint_rn(val);
            v[p] = x > 65535u ? 65535u : x;
        }
        uint4 w;
        w.x = v[0] | (v[1] << 16); w.y = v[2] | (v[3] << 16);
        w.z = v[4] | (v[5] << 16); w.w = v[6] | (v[7] << 16);
        int sw = r0 ^ (((c >> 3) & 7) << 3);
        *(uint4*)&sh[c * 136 + sw] = w;
    }
    __syncthreads();
    #pragma unroll
    for (int u = 0; u < 8; u++) {
        int idx = tid + 256 * u;
        int cl = idx >> 4;
        int rq = idx & 15;
        int sw = (rq * 8) ^ (((cl >> 3) & 7) << 3);
        uint4 w = *(const uint4*)&sh[cl * 136 + sw];
        *(uint4*)(CT + (size_t)(j0 + cl) * NPTS + i0 + rq * 8) = w;
    }
}

// ---------------------------------------------------------------------------
// merged softmin: grid (NPTS, 4). v = blockIdx.y selects the pass.
//   out[row] = -eps * ln sum_j exp((g[j] - C[row,j])/eps - lnN)
// with guaranteed-safe chunk pruning via per-chunk C mins and g min/max.
// ---------------------------------------------------------------------------
struct STab {
    const unsigned short* C[4];
    const unsigned short* cm[4];
    const float* g[4];
    const float* gmn[4];
    const float* gmx[4];
    float* out[4];
};

__global__ void __launch_bounds__(256)
softmin_all(STab tab, float inv_eps, float eps, float margin) {
    const int row = blockIdx.x;
    const int v   = blockIdx.y;
    const int tid = threadIdx.x;
    const int lane = tid & 31, w = tid >> 5;

    const unsigned short* __restrict__ Cq  = tab.C[v];
    const unsigned short* __restrict__ cm  = tab.cm[v];
    const float* __restrict__ g   = tab.g[v];
    const float* __restrict__ gmn = tab.gmn[v];
    const float* __restrict__ gmx = tab.gmx[v];

    __shared__ float s_lb[2];
    __shared__ int   s_list[NCHUNK];
    __shared__ int   s_cnt;
    __shared__ float s_m[8], s_s[8];

    // chunk bounds
    float lb = -1e30f, ub = -1e30f;
    if (tid < NCHUNK) {
        float cmf = (float)cm[(size_t)row * NCHUNK + tid] * QINV;
        lb = gmn[tid] - cmf;
        ub = gmx[tid] - cmf;
    }
    float L = lb;
    #pragma unroll
    for (int o = 16; o > 0; o >>= 1) L = fmaxf(L, __shfl_xor_sync(0xffffffffu, L, o));
    if (lane == 0 && w < 2) s_lb[w] = L;
    if (tid == 0) s_cnt = 0;
    __syncthreads();
    float thresh = fmaxf(s_lb[0], s_lb[1]) - margin;
    if (tid < NCHUNK && ub >= thresh) {
        int k = atomicAdd(&s_cnt, 1);
        s_list[k] = tid;
    }
    __syncthreads();
    const int n = s_cnt;

    const float k1 = inv_eps * LOG2E_F;
    const float kq = -k1 * QINV;
    const float kb = NEG_LOG_N_F * LOG2E_F;
    const unsigned short* __restrict__ Crow = Cq + (size_t)row * NPTS;

    float m = -1e30f, s = 0.0f;
    for (int k = w; k < n; k += 8) {
        int c = s_list[k];
        uint2 cw  = *(const uint2*)(Crow + c * 128 + lane * 4);
        float4 gv = *(const float4*)(g + c * 128 + lane * 4);
        float t0 = fmaf(dec_lo(cw.x), kq, fmaf(gv.x, k1, kb));
        float t1 = fmaf(dec_hi(cw.x), kq, fmaf(gv.y, k1, kb));
        float t2 = fmaf(dec_lo(cw.y), kq, fmaf(gv.z, k1, kb));
        float t3 = fmaf(dec_hi(cw.y), kq, fmaf(gv.w, k1, kb));
        float tm = fmaxf(fmaxf(t0, t1), fmaxf(t2, t3));
        float ts = ex2_fast(t0 - tm) + ex2_fast(t1 - tm)
                 + ex2_fast(t2 - tm) + ex2_fast(t3 - tm);
        float M = fmaxf(m, tm);
        s = s * ex2_fast(m - M) + ts * ex2_fast(tm - M);
        m = M;
    }

    // warp-level (m,s) combine
    #pragma unroll
    for (int o = 16; o > 0; o >>= 1) {
        float m2 = __shfl_xor_sync(0xffffffffu, m, o);
        float s2 = __shfl_xor_sync(0xffffffffu, s, o);
        float M = fmaxf(m, m2);
        s = s * ex2_fast(m - M) + s2 * ex2_fast(m2 - M);
        m = M;
    }
    if (lane == 0) { s_m[w] = m; s_s[w] = s; }
    __syncthreads();
    if (tid == 0) {
        float M = s_m[0], S = s_s[0];
        #pragma unroll
        for (int i = 1; i < 8; i++) {
            float mi = s_m[i];
            float Mx = fmaxf(M, mi);
            S = S * ex2_fast(M - Mx) + s_s[i] * ex2_fast(mi - Mx);
            M = Mx;
        }
        tab.out[v][row] = -eps * LN2_F * (M + lg2_fast(S));
    }
}

// ---------------------------------------------------------------------------
// optional averaged update of the 4 potentials + per-chunk min/max stats of
// the (resulting) g vectors, in softmin v-order: {gab, fba, faa, gbb}.
// grid 64 blocks x 128 threads; block c covers elements [c*128, c*128+128).
// ---------------------------------------------------------------------------
__global__ void __launch_bounds__(128)
update_stats(float* __restrict__ fba, const float* __restrict__ ft,
             float* __restrict__ gab, const float* __restrict__ gt,
             float* __restrict__ faa, const float* __restrict__ fs,
             float* __restrict__ gbb, const float* __restrict__ gs,
             float* __restrict__ gstat, int do_update) {
    const int c = blockIdx.x;
    const int t = threadIdx.x;
    const int i = c * 128 + t;
    const int lane = t & 31, w = t >> 5;

    float vfba, vgab, vfaa, vgbb;
    if (do_update) {
        vfba = 0.5f * (fba[i] + ft[i]);  fba[i] = vfba;
        vgab = 0.5f * (gab[i] + gt[i]);  gab[i] = vgab;
        vfaa = 0.5f * (faa[i] + fs[i]);  faa[i] = vfaa;
        vgbb = 0.5f * (gbb[i] + gs[i]);  gbb[i] = vgbb;
    } else {
        vfba = fba[i]; vgab = gab[i]; vfaa = faa[i]; vgbb = gbb[i];
    }

    float vals[4] = {vgab, vfba, vfaa, vgbb};   // softmin v-order
    __shared__ float smn[4][4], smx[4][4];
    #pragma unroll
    for (int k = 0; k < 4; k++) {
        float mn = vals[k], mx = vals[k];
        #pragma unroll
        for (int o = 16; o > 0; o >>= 1) {
            mn = fminf(mn, __shfl_xor_sync(0xffffffffu, mn, o));
            mx = fmaxf(mx, __shfl_xor_sync(0xffffffffu, mx, o));
        }
        if (lane == 0) { smn[w][k] = mn; smx[w][k] = mx; }
    }
    __syncthreads();
    if (t < 4) {
        float mn = fminf(fminf(smn[0][t], smn[1][t]), fminf(smn[2][t], smn[3][t]));
        float mx = fmaxf(fmaxf(smx[0][t], smx[1][t]), fmaxf(smx[2][t], smx[3][t]));
        gstat[t * NCHUNK + c]                = mn;
        gstat[4 * NCHUNK + t * NCHUNK + c]   = mx;
    }
}

// ---------------------------------------------------------------------------
__global__ void final_kernel(const float* __restrict__ fbf, const float* __restrict__ faf,
                             const float* __restrict__ gaf, const float* __restrict__ gbf,
                             float* __restrict__ out) {
    __shared__ float sh[256];
    float s = 0.0f;
    for (int i = threadIdx.x; i < NPTS; i += 256)
        s += (fbf[i] - faf[i]) + (gaf[i] - gbf[i]);
    sh[threadIdx.x] = s;
    __syncthreads();
    #pragma unroll
    for (int o = 128; o > 0; o >>= 1) {
        if (threadIdx.x < o) sh[threadIdx.x] += sh[threadIdx.x + o];
        __syncthreads();
    }
    if (threadIdx.x == 0) out[0] = sh[0] * (1.0f / (float)NPTS);
}

// ---------------------------------------------------------------------------
extern "C" void kernel_launch(void* const* d_in, const int* in_sizes, int n_in,
                              void* d_out, int out_size) {
    (void)in_sizes; (void)n_in; (void)out_size;
    const float* x = (const float*)d_in[0];
    const float* y = (const float*)d_in[1];
    float* out = (float*)d_out;

    unsigned short *cq = nullptr, *cmn = nullptr;
    float *vec = nullptr, *gstat = nullptr;
    cudaGetSymbolAddress((void**)&cq,    d_cq);
    cudaGetSymbolAddress((void**)&cmn,   d_cmin);
    cudaGetSymbolAddress((void**)&vec,   d_vecbuf);
    cudaGetSymbolAddress((void**)&gstat, d_gstat);

    unsigned short* Cxy = cq;
    unsigned short* Cyx = cq + NN;
    unsigned short* Cxx = cq + 2 * NN;
    unsigned short* Cyy = cq + 3 * NN;
    unsigned short* Mxy = cmn;
    unsigned short* Myx = cmn + (size_t)NPTS * NCHUNK;
    unsigned short* Mxx = cmn + 2 * (size_t)NPTS * NCHUNK;
    unsigned short* Myy = cmn + 3 * (size_t)NPTS * NCHUNK;

    float* hx   = vec + (size_t)V_HX   * NPTS;
    float* hy   = vec + (size_t)V_HY   * NPTS;
    float* zero = vec + (size_t)V_ZERO * NPTS;
    float* faa  = vec + (size_t)V_FAA  * NPTS;
    float* gbb  = vec + (size_t)V_GBB  * NPTS;
    float* gab  = vec + (size_t)V_GAB  * NPTS;
    float* fba  = vec + (size_t)V_FBA  * NPTS;
    float* ft   = vec + (size_t)V_FT   * NPTS;
    float* gt   = vec + (size_t)V_GT   * NPTS;
    float* fs   = vec + (size_t)V_FS   * NPTS;
    float* gs   = vec + (size_t)V_GS   * NPTS;

    static const float EPS[11] = {1024.0f, 256.0f, 64.0f, 16.0f, 4.0f, 1.0f,
                                  0.25f, 0.0625f, 0.015625f, 0.00390625f, 0.0025f};

    halfnorm_kernel<<<1024, 256>>>(x, hx);
    halfnorm_kernel<<<1024, 256>>>(y, hy);

    dim3 gg(64, 64);
    gemm_cost_q<<<gg, 256>>>(x, y, hx, hy, Cxy, Cyx, Mxy, Myx, 0);
    gemm_cost_q<<<gg, 256>>>(x, x, hx, hx, Cxx, Cxx, Mxx, Mxx, 1);
    gemm_cost_q<<<gg, 256>>>(y, y, hy, hy, Cyy, Cyy, Myy, Myy, 1);

    // init round: g = 0 for all four passes (zero vec serves as g and stats)
    STab init_tab;
    init_tab.C[0] = Cxx; init_tab.cm[0] = Mxx; init_tab.out[0] = faa;
    init_tab.C[1] = Cyy; init_tab.cm[1] = Myy; init_tab.out[1] = gbb;
    init_tab.C[2] = Cyx; init_tab.cm[2] = Myx; init_tab.out[2] = gab;
    init_tab.C[3] = Cxy; init_tab.cm[3] = Mxy; init_tab.out[3] = fba;
    for (int v = 0; v < 4; v++) {
        init_tab.g[v] = zero; init_tab.gmn[v] = zero; init_tab.gmx[v] = zero;
    }

    STab loop_tab;
    loop_tab.C[0] = Cxy; loop_tab.cm[0] = Mxy; loop_tab.g[0] = gab; loop_tab.out[0] = ft;
    loop_tab.C[1] = Cyx; loop_tab.cm[1] = Myx; loop_tab.g[1] = fba; loop_tab.out[1] = gt;
    loop_tab.C[2] = Cxx; loop_tab.cm[2] = Mxx; loop_tab.g[2] = faa; loop_tab.out[2] = fs;
    loop_tab.C[3] = Cyy; loop_tab.cm[3] = Myy; loop_tab.g[3] = gbb; loop_tab.out[3] = gs;
    for (int v = 0; v < 4; v++) {
        loop_tab.gmn[v] = gstat + v * NCHUNK;
        loop_tab.gmx[v] = gstat + 4 * NCHUNK + v * NCHUNK;
    }

    dim3 sg(NPTS, 4);
    {
        float e0 = EPS[0];
        softmin_all<<<sg, 256>>>(init_tab, 1.0f / e0, e0, PRUNE_MARGIN * e0);
    }
    // stats of post-init potentials (no update)
    update_stats<<<NCHUNK, 128>>>(fba, ft, gab, gt, faa, fs, gbb, gs, gstat, 0);

    for (int it = 0; it < 11; it++) {
        float e = EPS[it];
        softmin_all<<<sg, 256>>>(loop_tab, 1.0f / e, e, PRUNE_MARGIN * e);
        update_stats<<<NCHUNK, 128>>>(fba, ft, gab, gt, faa, fs, gbb, gs, gstat, 1);
    }

    {   // final non-averaged extrapolation at eps = blur^p
        float ef = EPS[10];
        softmin_all<<<sg, 256>>>(loop_tab, 1.0f / ef, ef, PRUNE_MARGIN * ef);
    }

    final_kernel<<<1, 256>>>(ft, fs, gt, gs, out);
}

// round 4
// speedup vs baseline: 1.5870x; 1.0004x over previous
#include <cuda_runtime.h>
#include <cstddef>

// ---------------------------------------------------------------------------
// Sinkhorn divergence (geomloss p=2, blur=0.05, scaling=0.5, diameter=32)
// N = M = 8192, D = 64.
// R3: merged 4-in-1 softmin launches, warp-shuffle LSE reductions, and
// hierarchical chunk pruning (per-row per-128-col chunk mins computed in the
// GEMM epilogue; chunks provably below the row max by >30 bits are skipped).
// ---------------------------------------------------------------------------

#define NPTS 8192
#define DIMS 64
#define NN      ((size_t)NPTS * (size_t)NPTS)
#define NCHUNK  64                       // 8192 / 128
#define QSCALE  128.0f
#define QINV    (1.0f / 128.0f)

__device__ __align__(256) unsigned short d_cq[4 * NN];              // 512 MB
__device__ __align__(256) unsigned short d_cmin[4 * NPTS * NCHUNK]; // 4 MB
__device__ __align__(256) float d_gstat[2 * 4 * NCHUNK];            // min|max
__device__ __align__(256) float d_vecbuf[11 * NPTS];

#define V_HX   0
#define V_HY   1
#define V_ZERO 2   // never written: zero from BSS (serves as zero g AND zero gstats)
#define V_FAA  3
#define V_GBB  4
#define V_GAB  5
#define V_FBA  6
#define V_FT   7
#define V_GT   8
#define V_FS   9
#define V_GS   10

#define LOG2E_F 1.4426950408889634f
#define LN2_F   0.6931471805599453f
#define NEG_LOG_N_F (-9.010913347279288f)   // -ln(8192)
#define PRUNE_MARGIN 20.794415f             // 30 * ln2

__device__ __forceinline__ float ex2_fast(float x) {
    float r; asm("ex2.approx.ftz.f32 %0, %1;" : "=f"(r) : "f"(x)); return r;
}
__device__ __forceinline__ float lg2_fast(float x) {
    float r; asm("lg2.approx.f32 %0, %1;" : "=f"(r) : "f"(x)); return r;
}
__device__ __forceinline__ float dec_lo(unsigned w) {
    return __uint_as_float(__byte_perm(w, 0x4B000000u, 0x7410)) - 8388608.0f;
}
__device__ __forceinline__ float dec_hi(unsigned w) {
    return __uint_as_float(__byte_perm(w, 0x4B000000u, 0x7432)) - 8388608.0f;
}

// ---------------------------------------------------------------------------
__global__ void halfnorm_kernel(const float* __restrict__ X, float* __restrict__ h) {
    int warp = (blockIdx.x * blockDim.x + threadIdx.x) >> 5;
    int lane = threadIdx.x & 31;
    if (warp >= NPTS) return;
    float v0 = X[(size_t)warp * DIMS + lane];
    float v1 = X[(size_t)warp * DIMS + 32 + lane];
    float s = v0 * v0 + v1 * v1;
    #pragma unroll
    for (int o = 16; o > 0; o >>= 1) s += __shfl_xor_sync(0xffffffffu, s, o);
    if (lane == 0) h[warp] = 0.5f * s;
}

// ---------------------------------------------------------------------------
// C[i,j] = quant(max(ha[i]+hb[j]-dot,0)); writes tile + transposed tile + the
// per-row chunk mins for both orientations. symmetric=1 skips lower triangle.
// ---------------------------------------------------------------------------
__global__ void __launch_bounds__(256)
gemm_cost_q(const float* __restrict__ A, const float* __restrict__ B,
            const float* __restrict__ ha, const float* __restrict__ hb,
            unsigned short* __restrict__ C, unsigned short* __restrict__ CT,
            unsigned short* __restrict__ cminC, unsigned short* __restrict__ cminCT,
            int symmetric) {
    int bi = blockIdx.y, bj = blockIdx.x;
    if (symmetric && bi > bj) return;
    const int i0 = bi * 128, j0 = bj * 128;

    __shared__ __align__(16) unsigned char smem_raw[34816];  // stages / u16 mirror
    __shared__ unsigned sm_r[2][128];
    __shared__ unsigned sm_c[4][128];
    float (*As)[132] = (float (*)[132])smem_raw;
    float (*Bs)[132] = (float (*)[132])(smem_raw + 16896);

    const int tid  = threadIdx.x;
    const int lane = tid & 31, warp = tid >> 5;
    const int wy = warp >> 1, wx = warp & 1;
    const int ty2 = lane & 3, tx2 = lane >> 2;
    const int r0 = wy * 32 + ty2 * 8;
    const int c0 = wx * 64 + tx2 * 8;

    float acc[8][8];
    #pragma unroll
    for (int p = 0; p < 8; p++)
        #pragma unroll
        for (int q = 0; q < 8; q++) acc[p][q] = 0.0f;

    #pragma unroll
    for (int kc = 0; kc < 2; kc++) {
        #pragma unroll
        for (int u = 0; u < 4; u++) {
            int idx = tid + 256 * u;
            int row = idx >> 3;
            int kq  = idx & 7;
            float4 av = *(const float4*)(A + (size_t)(i0 + row) * DIMS + kc * 32 + kq * 4);
            float4 bv = *(const float4*)(B + (size_t)(j0 + row) * DIMS + kc * 32 + kq * 4);
            As[kq * 4 + 0][row] = av.x; As[kq * 4 + 1][row] = av.y;
            As[kq * 4 + 2][row] = av.z; As[kq * 4 + 3][row] = av.w;
            Bs[kq * 4 + 0][row] = bv.x; Bs[kq * 4 + 1][row] = bv.y;
            Bs[kq * 4 + 2][row] = bv.z; Bs[kq * 4 + 3][row] = bv.w;
        }
        __syncthreads();

        #pragma unroll 4
        for (int k = 0; k < 32; k++) {
            float a[8], b[8];
            *(float4*)&a[0] = *(const float4*)&As[k][r0];
            *(float4*)&a[4] = *(const float4*)&As[k][r0 + 4];
            *(float4*)&b[0] = *(const float4*)&Bs[k][c0];
            *(float4*)&b[4] = *(const float4*)&Bs[k][c0 + 4];
            #pragma unroll
            for (int p = 0; p < 8; p++)
                #pragma unroll
                for (int q = 0; q < 8; q++)
                    acc[p][q] = fmaf(a[p], b[q], acc[p][q]);
        }
        __syncthreads();
    }

    float hav[8], hbv[8];
    #pragma unroll
    for (int p = 0; p < 8; p++) hav[p] = ha[i0 + r0 + p];
    #pragma unroll
    for (int q = 0; q < 8; q++) hbv[q] = hb[j0 + c0 + q];

    // direct tile store + row/col mins of quantized values
    unsigned colq[8];
    #pragma unroll
    for (int q = 0; q < 8; q++) colq[q] = 0xFFFFu;
    unsigned rowq[8];
    #pragma unroll
    for (int p = 0; p < 8; p++) {
        unsigned v[8], rmin = 0xFFFFu;
        #pragma unroll
        for (int q = 0; q < 8; q++) {
            float val = fmaxf(hav[p] + hbv[q] - acc[p][q], 0.0f) * QSCALE;
            unsigned x = __float2uint_rn(val);
            v[q] = x > 65535u ? 65535u : x;
            rmin = min(rmin, v[q]);
            colq[q] = min(colq[q], v[q]);
        }
        rowq[p] = rmin;
        uint4 w;
        w.x = v[0] | (v[1] << 16); w.y = v[2] | (v[3] << 16);
        w.z = v[4] | (v[5] << 16); w.w = v[6] | (v[7] << 16);
        *(uint4*)(C + (size_t)(i0 + r0 + p) * NPTS + j0 + c0) = w;
    }

    // reduce row mins over tx2 (lane bits 2..4), store per-wx half
    #pragma unroll
    for (int p = 0; p < 8; p++) {
        unsigned r = rowq[p];
        r = min(r, __shfl_xor_sync(0xffffffffu, r, 4));
        r = min(r, __shfl_xor_sync(0xffffffffu, r, 8));
        r = min(r, __shfl_xor_sync(0xffffffffu, r, 16));
        if (tx2 == 0) sm_r[wx][r0 + p] = r;
    }
    // reduce col mins over ty2 (lane bits 0..1), store per-wy quarter
    #pragma unroll
    for (int q = 0; q < 8; q++) {
        unsigned c = colq[q];
        c = min(c, __shfl_xor_sync(0xffffffffu, c, 1));
        c = min(c, __shfl_xor_sync(0xffffffffu, c, 2));
        if (ty2 == 0) sm_c[wy][c0 + q] = c;
    }
    __syncthreads();
    if (tid < 128) {
        unsigned rm = min(sm_r[0][tid], sm_r[1][tid]);
        cminC[(size_t)(i0 + tid) * NCHUNK + bj] = (unsigned short)rm;
        unsigned cm = min(min(sm_c[0][tid], sm_c[1][tid]),
                          min(sm_c[2][tid], sm_c[3][tid]));
        cminCT[(size_t)(j0 + tid) * NCHUNK + bi] = (unsigned short)cm;
    }

    // transposed tile via swizzled shared u16 staging
    __syncthreads();
    unsigned short* sh = (unsigned short*)smem_raw;
    #pragma unroll
    for (int q = 0; q < 8; q++) {
        int c = c0 + q;
        unsigned v[8];
        #pragma unroll
        for (int p = 0; p < 8; p++) {
            float val = fmaxf(hav[p] + hbv[q] - acc[p][q], 0.0f) * QSCALE;
            unsigned x = __float2uint_rn(val);
            v[p] = x > 65535u ? 65535u : x;
        }
        uint4 w;
        w.x = v[0] | (v[1] << 16); w.y = v[2] | (v[3] << 16);
        w.z = v[4] | (v[5] << 16); w.w = v[6] | (v[7] << 16);
        int sw = r0 ^ (((c >> 3) & 7) << 3);
        *(uint4*)&sh[c * 136 + sw] = w;
    }
    __syncthreads();
    #pragma unroll
    for (int u = 0; u < 8; u++) {
        int idx = tid + 256 * u;
        int cl = idx >> 4;
        int rq = idx & 15;
        int sw = (rq * 8) ^ (((cl >> 3) & 7) << 3);
        uint4 w = *(const uint4*)&sh[cl * 136 + sw];
        *(uint4*)(CT + (size_t)(j0 + cl) * NPTS + i0 + rq * 8) = w;
    }
}

// ---------------------------------------------------------------------------
// merged softmin: grid (NPTS, 4). v = blockIdx.y selects the pass.
//   out[row] = -eps * ln sum_j exp((g[j] - C[row,j])/eps - lnN)
// with guaranteed-safe chunk pruning via per-chunk C mins and g min/max.
// ---------------------------------------------------------------------------
struct STab {
    const unsigned short* C[4];
    const unsigned short* cm[4];
    const float* g[4];
    const float* gmn[4];
    const float* gmx[4];
    float* out[4];
};

__global__ void __launch_bounds__(256)
softmin_all(STab tab, float inv_eps, float eps, float margin) {
    const int row = blockIdx.x;
    const int v   = blockIdx.y;
    const int tid = threadIdx.x;
    const int lane = tid & 31, w = tid >> 5;

    const unsigned short* __restrict__ Cq  = tab.C[v];
    const unsigned short* __restrict__ cm  = tab.cm[v];
    const float* __restrict__ g   = tab.g[v];
    const float* __restrict__ gmn = tab.gmn[v];
    const float* __restrict__ gmx = tab.gmx[v];

    __shared__ float s_lb[2];
    __shared__ int   s_list[NCHUNK];
    __shared__ int   s_cnt;
    __shared__ float s_m[8], s_s[8];

    // chunk bounds
    float lb = -1e30f, ub = -1e30f;
    if (tid < NCHUNK) {
        float cmf = (float)cm[(size_t)row * NCHUNK + tid] * QINV;
        lb = gmn[tid] - cmf;
        ub = gmx[tid] - cmf;
    }
    float L = lb;
    #pragma unroll
    for (int o = 16; o > 0; o >>= 1) L = fmaxf(L, __shfl_xor_sync(0xffffffffu, L, o));
    if (lane == 0 && w < 2) s_lb[w] = L;
    if (tid == 0) s_cnt = 0;
    __syncthreads();
    float thresh = fmaxf(s_lb[0], s_lb[1]) - margin;
    if (tid < NCHUNK && ub >= thresh) {
        int k = atomicAdd(&s_cnt, 1);
        s_list[k] = tid;
    }
    __syncthreads();
    const int n = s_cnt;

    const float k1 = inv_eps * LOG2E_F;
    const float kq = -k1 * QINV;
    const float kb = NEG_LOG_N_F * LOG2E_F;
    const unsigned short* __restrict__ Crow = Cq + (size_t)row * NPTS;

    float m = -1e30f, s = 0.0f;
    for (int k = w; k < n; k += 8) {
        int c = s_list[k];
        uint2 cw  = *(const uint2*)(Crow + c * 128 + lane * 4);
        float4 gv = *(const float4*)(g + c * 128 + lane * 4);
        float t0 = fmaf(dec_lo(cw.x), kq, fmaf(gv.x, k1, kb));
        float t1 = fmaf(dec_hi(cw.x), kq, fmaf(gv.y, k1, kb));
        float t2 = fmaf(dec_lo(cw.y), kq, fmaf(gv.z, k1, kb));
        float t3 = fmaf(dec_hi(cw.y), kq, fmaf(gv.w, k1, kb));
        float tm = fmaxf(fmaxf(t0, t1), fmaxf(t2, t3));
        float ts = ex2_fast(t0 - tm) + ex2_fast(t1 - tm)
                 + ex2_fast(t2 - tm) + ex2_fast(t3 - tm);
        float M = fmaxf(m, tm);
        s = s * ex2_fast(m - M) + ts * ex2_fast(tm - M);
        m = M;
    }

    // warp-level (m,s) combine
    #pragma unroll
    for (int o = 16; o > 0; o >>= 1) {
        float m2 = __shfl_xor_sync(0xffffffffu, m, o);
        float s2 = __shfl_xor_sync(0xffffffffu, s, o);
        float M = fmaxf(m, m2);
        s = s * ex2_fast(m - M) + s2 * ex2_fast(m2 - M);
        m = M;
    }
    if (lane == 0) { s_m[w] = m; s_s[w] = s; }
    __syncthreads();
    if (tid == 0) {
        float M = s_m[0], S = s_s[0];
        #pragma unroll
        for (int i = 1; i < 8; i++) {
            float mi = s_m[i];
            float Mx = fmaxf(M, mi);
            S = S * ex2_fast(M - Mx) + s_s[i] * ex2_fast(mi - Mx);
            M = Mx;
        }
        tab.out[v][row] = -eps * LN2_F * (M + lg2_fast(S));
    }
}

// ---------------------------------------------------------------------------
// optional averaged update of the 4 potentials + per-chunk min/max stats of
// the (resulting) g vectors, in softmin v-order: {gab, fba, faa, gbb}.
// grid 64 blocks x 128 threads; block c covers elements [c*128, c*128+128).
// ---------------------------------------------------------------------------
__global__ void __launch_bounds__(128)
update_stats(float* __restrict__ fba, const float* __restrict__ ft,
             float* __restrict__ gab, const float* __restrict__ gt,
             float* __restrict__ faa, const float* __restrict__ fs,
             float* __restrict__ gbb, const float* __restrict__ gs,
             float* __restrict__ gstat, int do_update) {
    const int c = blockIdx.x;
    const int t = threadIdx.x;
    const int i = c * 128 + t;
    const int lane = t & 31, w = t >> 5;

    float vfba, vgab, vfaa, vgbb;
    if (do_update) {
        vfba = 0.5f * (fba[i] + ft[i]);  fba[i] = vfba;
        vgab = 0.5f * (gab[i] + gt[i]);  gab[i] = vgab;
        vfaa = 0.5f * (faa[i] + fs[i]);  faa[i] = vfaa;
        vgbb = 0.5f * (gbb[i] + gs[i]);  gbb[i] = vgbb;
    } else {
        vfba = fba[i]; vgab = gab[i]; vfaa = faa[i]; vgbb = gbb[i];
    }

    float vals[4] = {vgab, vfba, vfaa, vgbb};   // softmin v-order
    __shared__ float smn[4][4], smx[4][4];
    #pragma unroll
    for (int k = 0; k < 4; k++) {
        float mn = vals[k], mx = vals[k];
        #pragma unroll
        for (int o = 16; o > 0; o >>= 1) {
            mn = fminf(mn, __shfl_xor_sync(0xffffffffu, mn, o));
            mx = fmaxf(mx, __shfl_xor_sync(0xffffffffu, mx, o));
        }
        if (lane == 0) { smn[w][k] = mn; smx[w][k] = mx; }
    }
    __syncthreads();
    if (t < 4) {
        float mn = fminf(fminf(smn[0][t], smn[1][t]), fminf(smn[2][t], smn[3][t]));
        float mx = fmaxf(fmaxf(smx[0][t], smx[1][t]), fmaxf(smx[2][t], smx[3][t]));
        gstat[t * NCHUNK + c]                = mn;
        gstat[4 * NCHUNK + t * NCHUNK + c]   = mx;
    }
}

// ---------------------------------------------------------------------------
__global__ void final_kernel(const float* __restrict__ fbf, const float* __restrict__ faf,
                             const float* __restrict__ gaf, const float* __restrict__ gbf,
                             float* __restrict__ out) {
    __shared__ float sh[256];
    float s = 0.0f;
    for (int i = threadIdx.x; i < NPTS; i += 256)
        s += (fbf[i] - faf[i]) + (gaf[i] - gbf[i]);
    sh[threadIdx.x] = s;
    __syncthreads();
    #pragma unroll
    for (int o = 128; o > 0; o >>= 1) {
        if (threadIdx.x < o) sh[threadIdx.x] += sh[threadIdx.x + o];
        __syncthreads();
    }
    if (threadIdx.x == 0) out[0] = sh[0] * (1.0f / (float)NPTS);
}

// ---------------------------------------------------------------------------
extern "C" void kernel_launch(void* const* d_in, const int* in_sizes, int n_in,
                              void* d_out, int out_size) {
    (void)in_sizes; (void)n_in; (void)out_size;
    const float* x = (const float*)d_in[0];
    const float* y = (const float*)d_in[1];
    float* out = (float*)d_out;

    unsigned short *cq = nullptr, *cmn = nullptr;
    float *vec = nullptr, *gstat = nullptr;
    cudaGetSymbolAddress((void**)&cq,    d_cq);
    cudaGetSymbolAddress((void**)&cmn,   d_cmin);
    cudaGetSymbolAddress((void**)&vec,   d_vecbuf);
    cudaGetSymbolAddress((void**)&gstat, d_gstat);

    unsigned short* Cxy = cq;
    unsigned short* Cyx = cq + NN;
    unsigned short* Cxx = cq + 2 * NN;
    unsigned short* Cyy = cq + 3 * NN;
    unsigned short* Mxy = cmn;
    unsigned short* Myx = cmn + (size_t)NPTS * NCHUNK;
    unsigned short* Mxx = cmn + 2 * (size_t)NPTS * NCHUNK;
    unsigned short* Myy = cmn + 3 * (size_t)NPTS * NCHUNK;

    float* hx   = vec + (size_t)V_HX   * NPTS;
    float* hy   = vec + (size_t)V_HY   * NPTS;
    float* zero = vec + (size_t)V_ZERO * NPTS;
    float* faa  = vec + (size_t)V_FAA  * NPTS;
    float* gbb  = vec + (size_t)V_GBB  * NPTS;
    float* gab  = vec + (size_t)V_GAB  * NPTS;
    float* fba  = vec + (size_t)V_FBA  * NPTS;
    float* ft   = vec + (size_t)V_FT   * NPTS;
    float* gt   = vec + (size_t)V_GT   * NPTS;
    float* fs   = vec + (size_t)V_FS   * NPTS;
    float* gs   = vec + (size_t)V_GS   * NPTS;

    static const float EPS[11] = {1024.0f, 256.0f, 64.0f, 16.0f, 4.0f, 1.0f,
                                  0.25f, 0.0625f, 0.015625f, 0.00390625f, 0.0025f};

    halfnorm_kernel<<<1024, 256>>>(x, hx);
    halfnorm_kernel<<<1024, 256>>>(y, hy);

    dim3 gg(64, 64);
    gemm_cost_q<<<gg, 256>>>(x, y, hx, hy, Cxy, Cyx, Mxy, Myx, 0);
    gemm_cost_q<<<gg, 256>>>(x, x, hx, hx, Cxx, Cxx, Mxx, Mxx, 1);
    gemm_cost_q<<<gg, 256>>>(y, y, hy, hy, Cyy, Cyy, Myy, Myy, 1);

    // init round: g = 0 for all four passes (zero vec serves as g and stats)
    STab init_tab;
    init_tab.C[0] = Cxx; init_tab.cm[0] = Mxx; init_tab.out[0] = faa;
    init_tab.C[1] = Cyy; init_tab.cm[1] = Myy; init_tab.out[1] = gbb;
    init_tab.C[2] = Cyx; init_tab.cm[2] = Myx; init_tab.out[2] = gab;
    init_tab.C[3] = Cxy; init_tab.cm[3] = Mxy; init_tab.out[3] = fba;
    for (int v = 0; v < 4; v++) {
        init_tab.g[v] = zero; init_tab.gmn[v] = zero; init_tab.gmx[v] = zero;
    }

    STab loop_tab;
    loop_tab.C[0] = Cxy; loop_tab.cm[0] = Mxy; loop_tab.g[0] = gab; loop_tab.out[0] = ft;
    loop_tab.C[1] = Cyx; loop_tab.cm[1] = Myx; loop_tab.g[1] = fba; loop_tab.out[1] = gt;
    loop_tab.C[2] = Cxx; loop_tab.cm[2] = Mxx; loop_tab.g[2] = faa; loop_tab.out[2] = fs;
    loop_tab.C[3] = Cyy; loop_tab.cm[3] = Myy; loop_tab.g[3] = gbb; loop_tab.out[3] = gs;
    for (int v = 0; v < 4; v++) {
        loop_tab.gmn[v] = gstat + v * NCHUNK;
        loop_tab.gmx[v] = gstat + 4 * NCHUNK + v * NCHUNK;
    }

    dim3 sg(NPTS, 4);
    {
        float e0 = EPS[0];
        softmin_all<<<sg, 256>>>(init_tab, 1.0f / e0, e0, PRUNE_MARGIN * e0);
    }
    // stats of post-init potentials (no update)
    update_stats<<<NCHUNK, 128>>>(fba, ft, gab, gt, faa, fs, gbb, gs, gstat, 0);

    for (int it = 0; it < 11; it++) {
        float e = EPS[it];
        softmin_all<<<sg, 256>>>(loop_tab, 1.0f / e, e, PRUNE_MARGIN * e);
        update_stats<<<NCHUNK, 128>>>(fba, ft, gab, gt, faa, fs, gbb, gs, gstat, 1);
    }

    {   // final non-averaged extrapolation at eps = blur^p
        float ef = EPS[10];
        softmin_all<<<sg, 256>>>(loop_tab, 1.0f / ef, ef, PRUNE_MARGIN * ef);
    }

    final_kernel<<<1, 256>>>(ft, fs, gt, gs, out);
}

// round 5
// speedup vs baseline: 1.6107x; 1.0149x over previous
#include <cuda_runtime.h>
#include <cstddef>

// ---------------------------------------------------------------------------
// Sinkhorn divergence (geomloss p=2, blur=0.05, scaling=0.5, diameter=32)
// N = M = 8192, D = 64.  R5 (= completed R4 design):
// 3 stored u16 cost matrices (Cxy, Cxx upper, Cyy upper). Per round one
// streaming pass: Cxy tiles give row+col LSE partials; upper-tri tiles of
// Cxx/Cyy give rows + mirror rows. Mode A (eps>=16): factored exponential,
// 1 ex2/elem for both directions. Mode B (eps<=4): running anchors + 30-bit
// group skip. Stage 2 LSE-combines 64 (anchor,sum) partials per row.
// ---------------------------------------------------------------------------

#define NPTS 8192
#define DIMS 64
#define NN      ((size_t)NPTS * (size_t)NPTS)
#define NCHUNK  64
#define QSCALE  128.0f
#define QINV    (1.0f / 128.0f)
#define NTILES_XY  4096
#define NTILES_SYM 2080
#define NTILES_ALL (NTILES_XY + 2 * NTILES_SYM)

#define LOG2E_F 1.4426950408889634f
#define LN2_F   0.6931471805599453f
#define NEG_LOG_N_F (-9.010913347279288f)   // -ln(8192)
#define SKIP_BITS 30.0f

__device__ __align__(256) unsigned short d_cq[3 * NN];               // 384 MB
__device__ __align__(256) float2 d_part[4 * (size_t)NCHUNK * NPTS];  // 16 MB
__device__ __align__(256) float  d_tilemin[3 * 4096];
__device__ __align__(256) float  d_vecbuf[11 * NPTS];
__device__ __align__(256) unsigned d_gmaxe[4];   // order-encoded float max

#define V_HX 0
#define V_HY 1
#define V_ZERO 2
#define V_FAA 3
#define V_GBB 4
#define V_GAB 5
#define V_FBA 6
#define V_FT 7
#define V_GT 8
#define V_FS 9
#define V_GS 10

__device__ __forceinline__ float ex2_fast(float x) {
    float r; asm("ex2.approx.ftz.f32 %0, %1;" : "=f"(r) : "f"(x)); return r;
}
__device__ __forceinline__ float lg2_fast(float x) {
    float r; asm("lg2.approx.f32 %0, %1;" : "=f"(r) : "f"(x)); return r;
}
__device__ __forceinline__ float dec_lo(unsigned w) {
    return __uint_as_float(__byte_perm(w, 0x4B000000u, 0x7410)) - 8388608.0f;
}
__device__ __forceinline__ float dec_hi(unsigned w) {
    return __uint_as_float(__byte_perm(w, 0x4B000000u, 0x7432)) - 8388608.0f;
}
__device__ __forceinline__ unsigned enc_f(float f) {
    unsigned u = __float_as_uint(f);
    return (u & 0x80000000u) ? ~u : (u | 0x80000000u);
}
__device__ __forceinline__ float dec_f(unsigned u) {
    return __uint_as_float((u & 0x80000000u) ? (u ^ 0x80000000u) : ~u);
}

// ---------------------------------------------------------------------------
__global__ void halfnorm_kernel(const float* __restrict__ X, float* __restrict__ h) {
    int warp = (blockIdx.x * blockDim.x + threadIdx.x) >> 5;
    int lane = threadIdx.x & 31;
    if (warp >= NPTS) return;
    float v0 = X[(size_t)warp * DIMS + lane];
    float v1 = X[(size_t)warp * DIMS + 32 + lane];
    float s = v0 * v0 + v1 * v1;
    #pragma unroll
    for (int o = 16; o > 0; o >>= 1) s += __shfl_xor_sync(0xffffffffu, s, o);
    if (lane == 0) h[warp] = 0.5f * s;
}

__global__ void reset_gmax(float v) {
    if (threadIdx.x < 4) d_gmaxe[threadIdx.x] = enc_f(v);
}

// ---------------------------------------------------------------------------
// C[i,j] = quant(max(ha[i]+hb[j]-dot,0)) u16, + per-tile min (q-units, float).
// symmetric=1: only upper-triangle tiles written.
// ---------------------------------------------------------------------------
__global__ void __launch_bounds__(256)
gemm_cost_q(const float* __restrict__ A, const float* __restrict__ B,
            const float* __restrict__ ha, const float* __restrict__ hb,
            unsigned short* __restrict__ C, float* __restrict__ tileminf,
            int symmetric) {
    int bi = blockIdx.y, bj = blockIdx.x;
    if (symmetric && bi > bj) return;
    const int i0 = bi * 128, j0 = bj * 128;

    __shared__ float As[32][132];
    __shared__ float Bs[32][132];
    __shared__ unsigned sm_min[8];

    const int tid = threadIdx.x;
    const int lane = tid & 31, warp = tid >> 5;
    const int wy = warp >> 1, wx = warp & 1;
    const int ty2 = lane & 3, tx2 = lane >> 2;
    const int r0 = wy * 32 + ty2 * 8;
    const int c0 = wx * 64 + tx2 * 8;

    float acc[8][8];
    #pragma unroll
    for (int p = 0; p < 8; p++)
        #pragma unroll
        for (int q = 0; q < 8; q++) acc[p][q] = 0.0f;

    #pragma unroll
    for (int kc = 0; kc < 2; kc++) {
        #pragma unroll
        for (int u = 0; u < 4; u++) {
            int idx = tid + 256 * u;
            int row = idx >> 3, kq = idx & 7;
            float4 av = *(const float4*)(A + (size_t)(i0 + row) * DIMS + kc * 32 + kq * 4);
            float4 bv = *(const float4*)(B + (size_t)(j0 + row) * DIMS + kc * 32 + kq * 4);
            As[kq * 4 + 0][row] = av.x; As[kq * 4 + 1][row] = av.y;
            As[kq * 4 + 2][row] = av.z; As[kq * 4 + 3][row] = av.w;
            Bs[kq * 4 + 0][row] = bv.x; Bs[kq * 4 + 1][row] = bv.y;
            Bs[kq * 4 + 2][row] = bv.z; Bs[kq * 4 + 3][row] = bv.w;
        }
        __syncthreads();
        #pragma unroll 4
        for (int k = 0; k < 32; k++) {
            float a[8], b[8];
            *(float4*)&a[0] = *(const float4*)&As[k][r0];
            *(float4*)&a[4] = *(const float4*)&As[k][r0 + 4];
            *(float4*)&b[0] = *(const float4*)&Bs[k][c0];
            *(float4*)&b[4] = *(const float4*)&Bs[k][c0 + 4];
            #pragma unroll
            for (int p = 0; p < 8; p++)
                #pragma unroll
                for (int q = 0; q < 8; q++)
                    acc[p][q] = fmaf(a[p], b[q], acc[p][q]);
        }
        __syncthreads();
    }

    float hav[8], hbv[8];
    #pragma unroll
    for (int p = 0; p < 8; p++) hav[p] = ha[i0 + r0 + p];
    #pragma unroll
    for (int q = 0; q < 8; q++) hbv[q] = hb[j0 + c0 + q];

    unsigned tvmin = 0xFFFFu;
    #pragma unroll
    for (int p = 0; p < 8; p++) {
        unsigned v[8];
        #pragma unroll
        for (int q = 0; q < 8; q++) {
            float val = fmaxf(hav[p] + hbv[q] - acc[p][q], 0.0f) * QSCALE;
            unsigned x = __float2uint_rn(val);
            v[q] = x > 65535u ? 65535u : x;
            tvmin = min(tvmin, v[q]);
        }
        uint4 w;
        w.x = v[0] | (v[1] << 16); w.y = v[2] | (v[3] << 16);
        w.z = v[4] | (v[5] << 16); w.w = v[6] | (v[7] << 16);
        *(uint4*)(C + (size_t)(i0 + r0 + p) * NPTS + j0 + c0) = w;
    }
    #pragma unroll
    for (int o = 16; o > 0; o >>= 1)
        tvmin = min(tvmin, __shfl_xor_sync(0xffffffffu, tvmin, o));
    if (lane == 0) sm_min[warp] = tvmin;
    __syncthreads();
    if (tid == 0) {
        unsigned mn = sm_min[0];
        #pragma unroll
        for (int i = 1; i < 8; i++) mn = min(mn, sm_min[i]);
        tileminf[bi * 64 + bj] = (float)mn;
    }
}

// ---------------------------------------------------------------------------
// tile id decode: [0,4096) XY; then XX upper; then YY upper
// ---------------------------------------------------------------------------
__device__ __forceinline__ void decode_tile(int x, int& mat, int& bi, int& bj, bool& diag) {
    if (x < NTILES_XY) { mat = 0; bi = x >> 6; bj = x & 63; diag = false; return; }
    int idx = x - NTILES_XY; mat = 1;
    if (idx >= NTILES_SYM) { idx -= NTILES_SYM; mat = 2; }
    int b = 0;
    while (idx >= 64 - b) { idx -= 64 - b; b++; }
    bi = b; bj = b + idx; diag = (bi == bj);
}

struct TA {
    const unsigned short* C[3];
    const float* tmin[3];
    const float* gr[3];   // row-pass weights  (XY: gab, XX: faa, YY: gbb)
    const float* gc[3];   // col-pass weights  (XY: fba, XX: faa, YY: gbb)
    float2* Pr[3];        // row partials      (XY->Pft, XX->Pfs, YY->Pgs)
    float2* Pc[3];        // col partials      (XY->Pgt, sym: same as Pr)
};

// ---------------------------------------------------------------------------
// Mode A (eps >= 16): factored exponential, per-tile anchor; 1 ex2/element.
// ---------------------------------------------------------------------------
__global__ void __launch_bounds__(256)
tile_softmin_A(TA ta, float k1, float kb) {
    int mat, bi, bj; bool diag;
    decode_tile(blockIdx.x, mat, bi, bj, diag);
    const int i0 = bi * 128, j0 = bj * 128;
    const unsigned short* __restrict__ C = ta.C[mat];

    __shared__ float Rj[128], Si[128];
    __shared__ float sm_r[2][128];
    __shared__ float sm_c[4][128];

    const int tid = threadIdx.x;
    const int lane = tid & 31, warp = tid >> 5;
    const int wy = warp >> 1, wx = warp & 1;
    const int ty2 = lane & 3, tx2 = lane >> 2;
    const int r0 = wy * 32 + ty2 * 8;
    const int c0 = wx * 64 + tx2 * 8;

    const int ri = (mat == 0) ? 0 : (mat + 1);
    const int ci = (mat == 0) ? 1 : (mat + 1);
    const float gmr = dec_f(d_gmaxe[ri]);
    const float gmc = dec_f(d_gmaxe[ci]);
    const float tminq = ta.tmin[mat][bi * 64 + bj];

    if (tid < 128) {
        Rj[tid] = ex2_fast((ta.gr[mat][j0 + tid] - gmr) * k1);
        Si[tid] = ex2_fast((ta.gc[mat][i0 + tid] - gmc) * k1);
    }
    __syncthreads();

    uint4 w[8];
    #pragma unroll
    for (int p = 0; p < 8; p++)
        w[p] = *(const uint4*)(C + (size_t)(i0 + r0 + p) * NPTS + j0 + c0);

    const float kq  = -k1 * QINV;
    const float c0f = -tminq * kq;

    float rj[8];
    #pragma unroll
    for (int q = 0; q < 8; q++) rj[q] = Rj[c0 + q];
    float cs[8];
    #pragma unroll
    for (int q = 0; q < 8; q++) cs[q] = 0.0f;
    float rs[8];

    #pragma unroll
    for (int p = 0; p < 8; p++) {
        float sp = Si[r0 + p];
        uint4 wq = w[p];
        float e0 = ex2_fast(fmaf(dec_lo(wq.x), kq, c0f));
        float e1 = ex2_fast(fmaf(dec_hi(wq.x), kq, c0f));
        float e2 = ex2_fast(fmaf(dec_lo(wq.y), kq, c0f));
        float e3 = ex2_fast(fmaf(dec_hi(wq.y), kq, c0f));
        float e4 = ex2_fast(fmaf(dec_lo(wq.z), kq, c0f));
        float e5 = ex2_fast(fmaf(dec_hi(wq.z), kq, c0f));
        float e6 = ex2_fast(fmaf(dec_lo(wq.w), kq, c0f));
        float e7 = ex2_fast(fmaf(dec_hi(wq.w), kq, c0f));
        rs[p] = e0 * rj[0] + e1 * rj[1] + e2 * rj[2] + e3 * rj[3]
              + e4 * rj[4] + e5 * rj[5] + e6 * rj[6] + e7 * rj[7];
        cs[0] = fmaf(e0, sp, cs[0]); cs[1] = fmaf(e1, sp, cs[1]);
        cs[2] = fmaf(e2, sp, cs[2]); cs[3] = fmaf(e3, sp, cs[3]);
        cs[4] = fmaf(e4, sp, cs[4]); cs[5] = fmaf(e5, sp, cs[5]);
        cs[6] = fmaf(e6, sp, cs[6]); cs[7] = fmaf(e7, sp, cs[7]);
    }

    #pragma unroll
    for (int p = 0; p < 8; p++) {
        float v = rs[p];
        v += __shfl_xor_sync(0xffffffffu, v, 4);
        v += __shfl_xor_sync(0xffffffffu, v, 8);
        v += __shfl_xor_sync(0xffffffffu, v, 16);
        if (tx2 == 0) sm_r[wx][r0 + p] = v;
    }
    #pragma unroll
    for (int q = 0; q < 8; q++) {
        float v = cs[q];
        v += __shfl_xor_sync(0xffffffffu, v, 1);
        v += __shfl_xor_sync(0xffffffffu, v, 2);
        if (ty2 == 0) sm_c[wy][c0 + q] = v;
    }
    __syncthreads();

    const float A_r = fmaf(k1, gmr, kb) + (-k1 * QINV) * tminq;
    const float A_c = fmaf(k1, gmc, kb) + (-k1 * QINV) * tminq;
    if (tid < 128) {
        float rsum = sm_r[0][tid] + sm_r[1][tid];
        ta.Pr[mat][(size_t)bj * NPTS + i0 + tid] = make_float2(A_r, rsum);
        if (!diag) {
            float csum = sm_c[0][tid] + sm_c[1][tid] + sm_c[2][tid] + sm_c[3][tid];
            ta.Pc[mat][(size_t)bi * NPTS + j0 + tid] = make_float2(A_c, csum);
        }
    }
}

// ---------------------------------------------------------------------------
// Mode B (eps <= 4): running anchors + 30-bit element-group exp skip.
// ---------------------------------------------------------------------------
__device__ __forceinline__ void ms_upd(float& mq, float& sq, float t) {
    if (t > mq) { sq = fmaf(sq, ex2_fast(mq - t), 1.0f); mq = t; }
    else        { sq += ex2_fast(t - mq); }
}

__global__ void __launch_bounds__(256)
tile_softmin_B(TA ta, float k1, float kb) {
    int mat, bi, bj; bool diag;
    decode_tile(blockIdx.x, mat, bi, bj, diag);
    const int i0 = bi * 128, j0 = bj * 128;
    const unsigned short* __restrict__ C = ta.C[mat];

    __shared__ float Gr[128], Gc[128];
    __shared__ float2 sm_r[2][128];
    __shared__ float2 sm_c[4][128];

    const int tid = threadIdx.x;
    const int lane = tid & 31, warp = tid >> 5;
    const int wy = warp >> 1, wx = warp & 1;
    const int ty2 = lane & 3, tx2 = lane >> 2;
    const int r0 = wy * 32 + ty2 * 8;
    const int c0 = wx * 64 + tx2 * 8;

    if (tid < 128) {
        Gr[tid] = fmaf(ta.gr[mat][j0 + tid], k1, kb);
        Gc[tid] = fmaf(ta.gc[mat][i0 + tid], k1, kb);
    }
    __syncthreads();

    uint4 w[8];
    #pragma unroll
    for (int p = 0; p < 8; p++)
        w[p] = *(const uint4*)(C + (size_t)(i0 + r0 + p) * NPTS + j0 + c0);

    const float kq = -k1 * QINV;
    float G[8];
    #pragma unroll
    for (int q = 0; q < 8; q++) G[q] = Gr[c0 + q];

    // rows
    #pragma unroll
    for (int p = 0; p < 8; p++) {
        uint4 wq = w[p];
        float m_ = -1e30f, s_ = 0.0f;
        float t0 = fmaf(dec_lo(wq.x), kq, G[0]);
        float t1 = fmaf(dec_hi(wq.x), kq, G[1]);
        float t2 = fmaf(dec_lo(wq.y), kq, G[2]);
        float t3 = fmaf(dec_hi(wq.y), kq, G[3]);
        float tg = fmaxf(fmaxf(t0, t1), fmaxf(t2, t3));
        if (tg > m_ - SKIP_BITS) {
            if (tg > m_) { s_ *= ex2_fast(m_ - tg); m_ = tg; }
            s_ += ex2_fast(t0 - m_) + ex2_fast(t1 - m_) + ex2_fast(t2 - m_) + ex2_fast(t3 - m_);
        }
        float t4 = fmaf(dec_lo(wq.z), kq, G[4]);
        float t5 = fmaf(dec_hi(wq.z), kq, G[5]);
        float t6 = fmaf(dec_lo(wq.w), kq, G[6]);
        float t7 = fmaf(dec_hi(wq.w), kq, G[7]);
        tg = fmaxf(fmaxf(t4, t5), fmaxf(t6, t7));
        if (tg > m_ - SKIP_BITS) {
            if (tg > m_) { s_ *= ex2_fast(m_ - tg); m_ = tg; }
            s_ += ex2_fast(t4 - m_) + ex2_fast(t5 - m_) + ex2_fast(t6 - m_) + ex2_fast(t7 - m_);
        }
        float mm = m_, ss = s_;
        #pragma unroll
        for (int o = 4; o <= 16; o <<= 1) {
            float m2 = __shfl_xor_sync(0xffffffffu, mm, o);
            float s2 = __shfl_xor_sync(0xffffffffu, ss, o);
            float M = fmaxf(mm, m2);
            ss = ss * ex2_fast(mm - M) + s2 * ex2_fast(m2 - M);
            mm = M;
        }
        if (tx2 == 0) sm_r[wx][r0 + p] = make_float2(mm, ss);
    }
    __syncthreads();
    if (tid < 128) {
        float2 a = sm_r[0][tid], b = sm_r[1][tid];
        float M = fmaxf(a.x, b.x);
        float S = a.y * ex2_fast(a.x - M) + b.y * ex2_fast(b.x - M);
        ta.Pr[mat][(size_t)bj * NPTS + i0 + tid] = make_float2(M, S);
    }
    if (diag) return;

    // cols
    float mc[8], sc[8];
    #pragma unroll
    for (int q = 0; q < 8; q++) { mc[q] = -1e30f; sc[q] = 0.0f; }
    #pragma unroll
    for (int p = 0; p < 8; p++) {
        float gcp = Gc[r0 + p];
        uint4 wq = w[p];
        float t0 = fmaf(dec_lo(wq.x), kq, gcp);
        float t1 = fmaf(dec_hi(wq.x), kq, gcp);
        float t2 = fmaf(dec_lo(wq.y), kq, gcp);
        float t3 = fmaf(dec_hi(wq.y), kq, gcp);
        float tg = fmaxf(fmaxf(t0, t1), fmaxf(t2, t3));
        float mn = fminf(fminf(mc[0], mc[1]), fminf(mc[2], mc[3]));
        if (tg > mn - SKIP_BITS) {
            ms_upd(mc[0], sc[0], t0); ms_upd(mc[1], sc[1], t1);
            ms_upd(mc[2], sc[2], t2); ms_upd(mc[3], sc[3], t3);
        }
        float t4 = fmaf(dec_lo(wq.z), kq, gcp);
        float t5 = fmaf(dec_hi(wq.z), kq, gcp);
        float t6 = fmaf(dec_lo(wq.w), kq, gcp);
        float t7 = fmaf(dec_hi(wq.w), kq, gcp);
        tg = fmaxf(fmaxf(t4, t5), fmaxf(t6, t7));
        mn = fminf(fminf(mc[4], mc[5]), fminf(mc[6], mc[7]));
        if (tg > mn - SKIP_BITS) {
            ms_upd(mc[4], sc[4], t4); ms_upd(mc[5], sc[5], t5);
            ms_upd(mc[6], sc[6], t6); ms_upd(mc[7], sc[7], t7);
        }
    }
    #pragma unroll
    for (int q = 0; q < 8; q++) {
        float mm = mc[q], ss = sc[q];
        #pragma unroll
        for (int o = 1; o <= 2; o <<= 1) {
            float m2 = __shfl_xor_sync(0xffffffffu, mm, o);
            float s2 = __shfl_xor_sync(0xffffffffu, ss, o);
            float M = fmaxf(mm, m2);
            ss = ss * ex2_fast(mm - M) + s2 * ex2_fast(m2 - M);
            mm = M;
        }
        if (ty2 == 0) sm_c[wy][c0 + q] = make_float2(mm, ss);
    }
    __syncthreads();
    if (tid < 128) {
        float2 a = sm_c[0][tid], b = sm_c[1][tid];
        float2 c = sm_c[2][tid], d = sm_c[3][tid];
        float M = fmaxf(fmaxf(a.x, b.x), fmaxf(c.x, d.x));
        float S = a.y * ex2_fast(a.x - M) + b.y * ex2_fast(b.x - M)
                + c.y * ex2_fast(c.x - M) + d.y * ex2_fast(d.x - M);
        ta.Pc[mat][(size_t)bi * NPTS + j0 + tid] = make_float2(M, S);
    }
}

// ---------------------------------------------------------------------------
// Stage 2: combine 64 (anchor,sum) partials per row -> potential value.
// grid (64, 4): blockIdx.y selects array. avg=1: v = 0.5*(old + v).
// Also records global max of each written potential into encoded d_gmaxe.
// ---------------------------------------------------------------------------
struct S2 {
    const float2* P[4];
    float* g[4];
    int gslot[4];
};

__global__ void __launch_bounds__(128)
stage2_all(S2 s2, float eps, int avg) {
    const int a = blockIdx.y;
    const int r = blockIdx.x * 128 + threadIdx.x;
    const float2* __restrict__ P = s2.P[a];

    float m = -1e30f, s = 0.0f;
    #pragma unroll 4
    for (int c = 0; c < NCHUNK; c++) {
        float2 p = P[(size_t)c * NPTS + r];
        float M = fmaxf(m, p.x);
        s = s * ex2_fast(m - M) + p.y * ex2_fast(p.x - M);
        m = M;
    }
    float val = -eps * LN2_F * (m + lg2_fast(s));
    if (avg) val = 0.5f * (s2.g[a][r] + val);
    s2.g[a][r] = val;

    // block max -> atomic encoded max
    __shared__ float red[128];
    float v = val;
    #pragma unroll
    for (int o = 16; o > 0; o >>= 1) v = fmaxf(v, __shfl_xor_sync(0xffffffffu, v, o));
    if ((threadIdx.x & 31) == 0) red[threadIdx.x >> 5] = v;
    __syncthreads();
    if (threadIdx.x == 0) {
        float M = fmaxf(fmaxf(red[0], red[1]), fmaxf(red[2], red[3]));
        atomicMax(&d_gmaxe[s2.gslot[a]], enc_f(M));
    }
}

// ---------------------------------------------------------------------------
__global__ void final_kernel(const float* __restrict__ fbf, const float* __restrict__ faf,
                             const float* __restrict__ gaf, const float* __restrict__ gbf,
                             float* __restrict__ out) {
    __shared__ float sh[256];
    float s = 0.0f;
    for (int i = threadIdx.x; i < NPTS; i += 256)
        s += (fbf[i] - faf[i]) + (gaf[i] - gbf[i]);
    sh[threadIdx.x] = s;
    __syncthreads();
    #pragma unroll
    for (int o = 128; o > 0; o >>= 1) {
        if (threadIdx.x < o) sh[threadIdx.x] += sh[threadIdx.x + o];
        __syncthreads();
    }
    if (threadIdx.x == 0) out[0] = sh[0] * (1.0f / (float)NPTS);
}

// ---------------------------------------------------------------------------
extern "C" void kernel_launch(void* const* d_in, const int* in_sizes, int n_in,
                              void* d_out, int out_size) {
    (void)in_sizes; (void)n_in; (void)out_size;
    const float* x = (const float*)d_in[0];
    const float* y = (const float*)d_in[1];
    float* out = (float*)d_out;

    unsigned short* cq = nullptr;
    float2* part = nullptr;
    float *vec = nullptr, *tmin = nullptr;
    cudaGetSymbolAddress((void**)&cq,   d_cq);
    cudaGetSymbolAddress((void**)&part, d_part);
    cudaGetSymbolAddress((void**)&vec,  d_vecbuf);
    cudaGetSymbolAddress((void**)&tmin, d_tilemin);

    unsigned short* Cxy = cq;
    unsigned short* Cxx = cq + NN;
    unsigned short* Cyy = cq + 2 * NN;
    float* Txy = tmin;
    float* Txx = tmin + 4096;
    float* Tyy = tmin + 2 * 4096;
    float2* Pft = part;
    float2* Pgt = part + (size_t)NCHUNK * NPTS;
    float2* Pfs = part + 2 * (size_t)NCHUNK * NPTS;
    float2* Pgs = part + 3 * (size_t)NCHUNK * NPTS;

    float* hx   = vec + (size_t)V_HX   * NPTS;
    float* hy   = vec + (size_t)V_HY   * NPTS;
    float* zero = vec + (size_t)V_ZERO * NPTS;
    float* faa  = vec + (size_t)V_FAA  * NPTS;
    float* gbb  = vec + (size_t)V_GBB  * NPTS;
    float* gab  = vec + (size_t)V_GAB  * NPTS;
    float* fba  = vec + (size_t)V_FBA  * NPTS;
    float* ft   = vec + (size_t)V_FT   * NPTS;
    float* gt   = vec + (size_t)V_GT   * NPTS;
    float* fs   = vec + (size_t)V_FS   * NPTS;
    float* gs   = vec + (size_t)V_GS   * NPTS;

    static const float EPS[11] = {1024.0f, 256.0f, 64.0f, 16.0f, 4.0f, 1.0f,
                                  0.25f, 0.0625f, 0.015625f, 0.00390625f, 0.0025f};

    halfnorm_kernel<<<1024, 256>>>(x, hx);
    halfnorm_kernel<<<1024, 256>>>(y, hy);

    dim3 gg(64, 64);
    gemm_cost_q<<<gg, 256>>>(x, y, hx, hy, Cxy, Txy, 0);
    gemm_cost_q<<<gg, 256>>>(x, x, hx, hx, Cxx, Txx, 1);
    gemm_cost_q<<<gg, 256>>>(y, y, hy, hy, Cyy, Tyy, 1);

    TA init_ta, ta;
    init_ta.C[0] = Cxy; init_ta.C[1] = Cxx; init_ta.C[2] = Cyy;
    init_ta.tmin[0] = Txy; init_ta.tmin[1] = Txx; init_ta.tmin[2] = Tyy;
    init_ta.Pr[0] = Pft; init_ta.Pc[0] = Pgt;
    init_ta.Pr[1] = Pfs; init_ta.Pc[1] = Pfs;
    init_ta.Pr[2] = Pgs; init_ta.Pc[2] = Pgs;
    for (int m = 0; m < 3; m++) { init_ta.gr[m] = zero; init_ta.gc[m] = zero; }
    ta = init_ta;
    ta.gr[0] = gab; ta.gc[0] = fba;
    ta.gr[1] = faa; ta.gc[1] = faa;
    ta.gr[2] = gbb; ta.gc[2] = gbb;

    // stage-2 tables: partial array a -> potential; gslot: gab->0, fba->1,
    // faa->2, gbb->3 (Mode A reads row slot=gr, col slot=gc).
    S2 s2_init, s2_loop, s2_fin;
    s2_init.P[0] = Pft; s2_init.P[1] = Pgt; s2_init.P[2] = Pfs; s2_init.P[3] = Pgs;
    s2_init.g[0] = fba; s2_init.g[1] = gab; s2_init.g[2] = faa; s2_init.g[3] = gbb;
    s2_init.gslot[0] = 1; s2_init.gslot[1] = 0; s2_init.gslot[2] = 2; s2_init.gslot[3] = 3;
    s2_loop = s2_init;
    s2_fin = s2_init;
    s2_fin.g[0] = ft; s2_fin.g[1] = gt; s2_fin.g[2] = fs; s2_fin.g[3] = gs;

    dim3 s2g(64, 4);

    // init round (eps0 = 1024, g = 0, gmax = 0)
    reset_gmax<<<1, 32>>>(0.0f);
    {
        float e0 = EPS[0], k1 = LOG2E_F / e0, kb = NEG_LOG_N_F * LOG2E_F;
        tile_softmin_A<<<NTILES_ALL, 256>>>(init_ta, k1, kb);
        reset_gmax<<<1, 32>>>(-1e30f);
        stage2_all<<<s2g, 128>>>(s2_init, e0, 0);
    }

    for (int it = 0; it < 11; it++) {
        float e = EPS[it], k1 = LOG2E_F / e, kb = NEG_LOG_N_F * LOG2E_F;
        if (e >= 16.0f) tile_softmin_A<<<NTILES_ALL, 256>>>(ta, k1, kb);
        else            tile_softmin_B<<<NTILES_ALL, 256>>>(ta, k1, kb);
        reset_gmax<<<1, 32>>>(-1e30f);
        stage2_all<<<s2g, 128>>>(s2_loop, e, 1);
    }

    {   // final extrapolation at eps = blur^p
        float ef = EPS[10], k1 = LOG2E_F / ef, kb = NEG_LOG_N_F * LOG2E_F;
        tile_softmin_B<<<NTILES_ALL, 256>>>(ta, k1, kb);
        reset_gmax<<<1, 32>>>(-1e30f);
        stage2_all<<<s2g, 128>>>(s2_fin, ef, 0);
    }

    final_kernel<<<1, 256>>>(ft, fs, gt, gs, out);
}

// round 6
// speedup vs baseline: 1.8321x; 1.1374x over previous
#include <cuda_runtime.h>
#include <cstddef>

// ---------------------------------------------------------------------------
// Sinkhorn divergence (geomloss p=2, blur=0.05, scaling=0.5, diameter=32)
// N = M = 8192, D = 64.  R6:
// Same 3-matrix fused row+col streaming as R5, but all in-tile reductions go
// through shared-memory two-phase combines (no shuffle-LSE chains), row+col
// processing merged into one loop (single decode), gmax via per-block maxima
// (no atomics / reset launches), GEMMs and halfnorms merged into one launch.
// ---------------------------------------------------------------------------

#define NPTS 8192
#define DIMS 64
#define NN      ((size_t)NPTS * (size_t)NPTS)
#define NCHUNK  64
#define QSCALE  128.0f
#define QINV    (1.0f / 128.0f)
#define NTILES_XY  4096
#define NTILES_SYM 2080
#define NTILES_ALL (NTILES_XY + 2 * NTILES_SYM)

#define LOG2E_F 1.4426950408889634f
#define LN2_F   0.6931471805599453f
#define NEG_LOG_N_F (-9.010913347279288f)   // -ln(8192)
#define SKIP_BITS 30.0f

__device__ __align__(256) unsigned short d_cq[3 * NN];               // 384 MB
__device__ __align__(256) float2 d_part[4 * (size_t)NCHUNK * NPTS];  // 16 MB
__device__ __align__(256) float  d_tilemin[3 * 4096];
__device__ __align__(256) float  d_vecbuf[11 * NPTS];
__device__ __align__(256) float  d_bmax[4 * 64];   // per-stage2-block maxima

#define V_HX 0
#define V_HY 1
#define V_ZERO 2
#define V_FAA 3
#define V_GBB 4
#define V_GAB 5
#define V_FBA 6
#define V_FT 7
#define V_GT 8
#define V_FS 9
#define V_GS 10

__device__ __forceinline__ float ex2_fast(float x) {
    float r; asm("ex2.approx.ftz.f32 %0, %1;" : "=f"(r) : "f"(x)); return r;
}
__device__ __forceinline__ float lg2_fast(float x) {
    float r; asm("lg2.approx.f32 %0, %1;" : "=f"(r) : "f"(x)); return r;
}
__device__ __forceinline__ float dec_lo(unsigned w) {
    return __uint_as_float(__byte_perm(w, 0x4B000000u, 0x7410)) - 8388608.0f;
}
__device__ __forceinline__ float dec_hi(unsigned w) {
    return __uint_as_float(__byte_perm(w, 0x4B000000u, 0x7432)) - 8388608.0f;
}

// ---------------------------------------------------------------------------
// prep: half-norms of x and y (one warp/row) + zero d_bmax
// ---------------------------------------------------------------------------
__global__ void prep_kernel(const float* __restrict__ x, const float* __restrict__ y,
                            float* __restrict__ hx, float* __restrict__ hy) {
    if (blockIdx.x == 0 && threadIdx.x < 256) d_bmax[threadIdx.x] = 0.0f;
    int gw = (blockIdx.x * blockDim.x + threadIdx.x) >> 5;
    int lane = threadIdx.x & 31;
    const float* X = (gw < NPTS) ? x : y;
    float* H = (gw < NPTS) ? hx : hy;
    int row = (gw < NPTS) ? gw : gw - NPTS;
    float v0 = X[(size_t)row * DIMS + lane];
    float v1 = X[(size_t)row * DIMS + 32 + lane];
    float s = v0 * v0 + v1 * v1;
    #pragma unroll
    for (int o = 16; o > 0; o >>= 1) s += __shfl_xor_sync(0xffffffffu, s, o);
    if (lane == 0) H[row] = 0.5f * s;
}

// ---------------------------------------------------------------------------
// merged GEMM: z=0 Cxy(x,y), z=1 Cxx(x,x) upper, z=2 Cyy(y,y) upper.
// C[i,j] = quant(max(ha[i]+hb[j]-dot,0)) u16, + per-tile min (q-units).
// ---------------------------------------------------------------------------
__global__ void __launch_bounds__(256)
gemm_cost_q(const float* __restrict__ x, const float* __restrict__ y,
            const float* __restrict__ hx, const float* __restrict__ hy,
            unsigned short* __restrict__ cq, float* __restrict__ tmin) {
    const int mz = blockIdx.z;
    int bi = blockIdx.y, bj = blockIdx.x;
    if (mz > 0 && bi > bj) return;
    const float* A  = (mz == 2) ? y : x;
    const float* B  = (mz == 0 || mz == 2) ? y : x;
    const float* ha = (mz == 2) ? hy : hx;
    const float* hb = (mz == 0 || mz == 2) ? hy : hx;
    unsigned short* C = cq + (size_t)mz * NN;
    float* tileminf = tmin + mz * 4096;

    const int i0 = bi * 128, j0 = bj * 128;
    __shared__ float As[32][132];
    __shared__ float Bs[32][132];
    __shared__ unsigned sm_min[8];

    const int tid = threadIdx.x;
    const int lane = tid & 31, warp = tid >> 5;
    const int wy = warp >> 1, wx = warp & 1;
    const int ty2 = lane & 3, tx2 = lane >> 2;
    const int r0 = wy * 32 + ty2 * 8;
    const int c0 = wx * 64 + tx2 * 8;

    float acc[8][8];
    #pragma unroll
    for (int p = 0; p < 8; p++)
        #pragma unroll
        for (int q = 0; q < 8; q++) acc[p][q] = 0.0f;

    #pragma unroll
    for (int kc = 0; kc < 2; kc++) {
        #pragma unroll
        for (int u = 0; u < 4; u++) {
            int idx = tid + 256 * u;
            int row = idx >> 3, kq = idx & 7;
            float4 av = *(const float4*)(A + (size_t)(i0 + row) * DIMS + kc * 32 + kq * 4);
            float4 bv = *(const float4*)(B + (size_t)(j0 + row) * DIMS + kc * 32 + kq * 4);
            As[kq * 4 + 0][row] = av.x; As[kq * 4 + 1][row] = av.y;
            As[kq * 4 + 2][row] = av.z; As[kq * 4 + 3][row] = av.w;
            Bs[kq * 4 + 0][row] = bv.x; Bs[kq * 4 + 1][row] = bv.y;
            Bs[kq * 4 + 2][row] = bv.z; Bs[kq * 4 + 3][row] = bv.w;
        }
        __syncthreads();
        #pragma unroll 4
        for (int k = 0; k < 32; k++) {
            float a[8], b[8];
            *(float4*)&a[0] = *(const float4*)&As[k][r0];
            *(float4*)&a[4] = *(const float4*)&As[k][r0 + 4];
            *(float4*)&b[0] = *(const float4*)&Bs[k][c0];
            *(float4*)&b[4] = *(const float4*)&Bs[k][c0 + 4];
            #pragma unroll
            for (int p = 0; p < 8; p++)
                #pragma unroll
                for (int q = 0; q < 8; q++)
                    acc[p][q] = fmaf(a[p], b[q], acc[p][q]);
        }
        __syncthreads();
    }

    float hav[8], hbv[8];
    #pragma unroll
    for (int p = 0; p < 8; p++) hav[p] = ha[i0 + r0 + p];
    #pragma unroll
    for (int q = 0; q < 8; q++) hbv[q] = hb[j0 + c0 + q];

    unsigned tvmin = 0xFFFFu;
    #pragma unroll
    for (int p = 0; p < 8; p++) {
        unsigned v[8];
        #pragma unroll
        for (int q = 0; q < 8; q++) {
            float val = fmaxf(hav[p] + hbv[q] - acc[p][q], 0.0f) * QSCALE;
            unsigned xq = __float2uint_rn(val);
            v[q] = xq > 65535u ? 65535u : xq;
            tvmin = min(tvmin, v[q]);
        }
        uint4 w;
        w.x = v[0] | (v[1] << 16); w.y = v[2] | (v[3] << 16);
        w.z = v[4] | (v[5] << 16); w.w = v[6] | (v[7] << 16);
        *(uint4*)(C + (size_t)(i0 + r0 + p) * NPTS + j0 + c0) = w;
    }
    #pragma unroll
    for (int o = 16; o > 0; o >>= 1)
        tvmin = min(tvmin, __shfl_xor_sync(0xffffffffu, tvmin, o));
    if (lane == 0) sm_min[warp] = tvmin;
    __syncthreads();
    if (tid == 0) {
        unsigned mn = sm_min[0];
        #pragma unroll
        for (int i = 1; i < 8; i++) mn = min(mn, sm_min[i]);
        tileminf[bi * 64 + bj] = (float)mn;
    }
}

// ---------------------------------------------------------------------------
__device__ __forceinline__ void decode_tile(int xx, int& mat, int& bi, int& bj, bool& diag) {
    if (xx < NTILES_XY) { mat = 0; bi = xx >> 6; bj = xx & 63; diag = false; return; }
    int idx = xx - NTILES_XY; mat = 1;
    if (idx >= NTILES_SYM) { idx -= NTILES_SYM; mat = 2; }
    int b = 0;
    while (idx >= 64 - b) { idx -= 64 - b; b++; }
    bi = b; bj = b + idx; diag = (bi == bj);
}

struct TA {
    const unsigned short* C[3];
    const float* tmin[3];
    const float* gr[3];   // row-pass weights (indexed by column j)
    const float* gc[3];   // col-pass weights (indexed by row i)
    float2* Pr[3];
    float2* Pc[3];
    int rslot[3], cslot[3];   // d_bmax slots for gr / gc (Mode A)
};

// ---------------------------------------------------------------------------
// Mode A (eps >= 16): factored exponential, per-tile anchor, 1 ex2/element.
// Reductions: plain sums via smem two-phase (threads 0-127 rows, 128-255 cols).
// ---------------------------------------------------------------------------
__global__ void __launch_bounds__(256)
tile_softmin_A(TA ta, float k1, float kb) {
    int mat, bi, bj; bool diag;
    decode_tile(blockIdx.x, mat, bi, bj, diag);
    const int i0 = bi * 128, j0 = bj * 128;
    const unsigned short* __restrict__ C = ta.C[mat];

    __shared__ float Rj[128], Si[128];
    __shared__ float s_gm[2];
    __shared__ float partR[128][17];
    __shared__ float partC[128][17];

    const int tid = threadIdx.x;
    const int lane = tid & 31, warp = tid >> 5;
    const int wy = warp >> 1, wx = warp & 1;
    const int ty2 = lane & 3, tx2 = lane >> 2;
    const int r0 = wy * 32 + ty2 * 8;
    const int c0 = wx * 64 + tx2 * 8;
    const int segR = wx * 8 + tx2;      // 0..15
    const int segC = wy * 4 + ty2;      // 0..15

    // reduce 64 per-block maxima -> global gmax for row/col weights
    if (warp < 2) {
        int slot = (warp == 0) ? ta.rslot[mat] : ta.cslot[mat];
        float v = fmaxf(d_bmax[slot * 64 + lane], d_bmax[slot * 64 + 32 + lane]);
        #pragma unroll
        for (int o = 16; o > 0; o >>= 1) v = fmaxf(v, __shfl_xor_sync(0xffffffffu, v, o));
        if (lane == 0) s_gm[warp] = v;
    }
    __syncthreads();
    const float gmr = s_gm[0], gmc = s_gm[1];
    const float tminq = ta.tmin[mat][bi * 64 + bj];

    if (tid < 128) {
        Rj[tid] = ex2_fast((ta.gr[mat][j0 + tid] - gmr) * k1);
        Si[tid] = ex2_fast((ta.gc[mat][i0 + tid] - gmc) * k1);
    }
    __syncthreads();

    uint4 w[8];
    #pragma unroll
    for (int p = 0; p < 8; p++)
        w[p] = *(const uint4*)(C + (size_t)(i0 + r0 + p) * NPTS + j0 + c0);

    const float kq  = -k1 * QINV;
    const float c0f = -tminq * kq;

    float rj[8];
    #pragma unroll
    for (int q = 0; q < 8; q++) rj[q] = Rj[c0 + q];
    float cs[8];
    #pragma unroll
    for (int q = 0; q < 8; q++) cs[q] = 0.0f;

    #pragma unroll
    for (int p = 0; p < 8; p++) {
        float sp = Si[r0 + p];
        uint4 wq = w[p];
        float e0 = ex2_fast(fmaf(dec_lo(wq.x), kq, c0f));
        float e1 = ex2_fast(fmaf(dec_hi(wq.x), kq, c0f));
        float e2 = ex2_fast(fmaf(dec_lo(wq.y), kq, c0f));
        float e3 = ex2_fast(fmaf(dec_hi(wq.y), kq, c0f));
        float e4 = ex2_fast(fmaf(dec_lo(wq.z), kq, c0f));
        float e5 = ex2_fast(fmaf(dec_hi(wq.z), kq, c0f));
        float e6 = ex2_fast(fmaf(dec_lo(wq.w), kq, c0f));
        float e7 = ex2_fast(fmaf(dec_hi(wq.w), kq, c0f));
        partR[r0 + p][segR] = e0 * rj[0] + e1 * rj[1] + e2 * rj[2] + e3 * rj[3]
                            + e4 * rj[4] + e5 * rj[5] + e6 * rj[6] + e7 * rj[7];
        cs[0] = fmaf(e0, sp, cs[0]); cs[1] = fmaf(e1, sp, cs[1]);
        cs[2] = fmaf(e2, sp, cs[2]); cs[3] = fmaf(e3, sp, cs[3]);
        cs[4] = fmaf(e4, sp, cs[4]); cs[5] = fmaf(e5, sp, cs[5]);
        cs[6] = fmaf(e6, sp, cs[6]); cs[7] = fmaf(e7, sp, cs[7]);
    }
    #pragma unroll
    for (int q = 0; q < 8; q++) partC[c0 + q][segC] = cs[q];
    __syncthreads();

    const float A_r = fmaf(k1, gmr, kb) + kq * tminq;
    const float A_c = fmaf(k1, gmc, kb) + kq * tminq;
    if (tid < 128) {
        float s = 0.0f;
        #pragma unroll
        for (int k = 0; k < 16; k++) s += partR[tid][k];
        ta.Pr[mat][(size_t)bj * NPTS + i0 + tid] = make_float2(A_r, s);
    } else if (!diag) {
        int j = tid - 128;
        float s = 0.0f;
        #pragma unroll
        for (int k = 0; k < 16; k++) s += partC[j][k];
        ta.Pc[mat][(size_t)bi * NPTS + j0 + j] = make_float2(A_c, s);
    }
}

// ---------------------------------------------------------------------------
// Mode B (eps < 16): per-group anchored partials, smem two-phase LSE combine,
// column accumulators with 30-bit group skip. No shuffle-LSE chains.
// ---------------------------------------------------------------------------
__device__ __forceinline__ void ms_upd(float& mq, float& sq, float t) {
    if (t > mq) { sq = fmaf(sq, ex2_fast(mq - t), 1.0f); mq = t; }
    else        { sq += ex2_fast(t - mq); }
}

__global__ void __launch_bounds__(256)
tile_softmin_B(TA ta, float k1, float kb) {
    int mat, bi, bj; bool diag;
    decode_tile(blockIdx.x, mat, bi, bj, diag);
    const int i0 = bi * 128, j0 = bj * 128;
    const unsigned short* __restrict__ C = ta.C[mat];

    __shared__ float Gr[128], Gc[128];
    __shared__ float2 partR[128][17];
    __shared__ float2 partC[128][17];

    const int tid = threadIdx.x;
    const int lane = tid & 31, warp = tid >> 5;
    const int wy = warp >> 1, wx = warp & 1;
    const int ty2 = lane & 3, tx2 = lane >> 2;
    const int r0 = wy * 32 + ty2 * 8;
    const int c0 = wx * 64 + tx2 * 8;
    const int segR = wx * 8 + tx2;
    const int segC = wy * 4 + ty2;

    if (tid < 128) {
        Gr[tid] = fmaf(ta.gr[mat][j0 + tid], k1, kb);
        Gc[tid] = fmaf(ta.gc[mat][i0 + tid], k1, kb);
    }
    __syncthreads();

    uint4 w[8];
    #pragma unroll
    for (int p = 0; p < 8; p++)
        w[p] = *(const uint4*)(C + (size_t)(i0 + r0 + p) * NPTS + j0 + c0);

    const float kq = -k1 * QINV;
    float G[8];
    #pragma unroll
    for (int q = 0; q < 8; q++) G[q] = Gr[c0 + q];

    float mc[8], sc[8];
    #pragma unroll
    for (int q = 0; q < 8; q++) { mc[q] = -1e30f; sc[q] = 0.0f; }

    #pragma unroll
    for (int p = 0; p < 8; p++) {
        uint4 wq = w[p];
        float d0 = dec_lo(wq.x), d1 = dec_hi(wq.x);
        float d2 = dec_lo(wq.y), d3 = dec_hi(wq.y);
        float d4 = dec_lo(wq.z), d5 = dec_hi(wq.z);
        float d6 = dec_lo(wq.w), d7 = dec_hi(wq.w);

        // rows: anchored group partial (no running state needed)
        float t0 = fmaf(d0, kq, G[0]), t1 = fmaf(d1, kq, G[1]);
        float t2 = fmaf(d2, kq, G[2]), t3 = fmaf(d3, kq, G[3]);
        float t4 = fmaf(d4, kq, G[4]), t5 = fmaf(d5, kq, G[5]);
        float t6 = fmaf(d6, kq, G[6]), t7 = fmaf(d7, kq, G[7]);
        float mp = fmaxf(fmaxf(fmaxf(t0, t1), fmaxf(t2, t3)),
                         fmaxf(fmaxf(t4, t5), fmaxf(t6, t7)));
        float sp = ex2_fast(t0 - mp) + ex2_fast(t1 - mp)
                 + ex2_fast(t2 - mp) + ex2_fast(t3 - mp)
                 + ex2_fast(t4 - mp) + ex2_fast(t5 - mp)
                 + ex2_fast(t6 - mp) + ex2_fast(t7 - mp);
        partR[r0 + p][segR] = make_float2(mp, sp);

        // cols: running (m,s) with 30-bit group skip
        float gcp = Gc[r0 + p];
        float u0 = fmaf(d0, kq, gcp), u1 = fmaf(d1, kq, gcp);
        float u2 = fmaf(d2, kq, gcp), u3 = fmaf(d3, kq, gcp);
        float u4 = fmaf(d4, kq, gcp), u5 = fmaf(d5, kq, gcp);
        float u6 = fmaf(d6, kq, gcp), u7 = fmaf(d7, kq, gcp);
        float ug = fmaxf(fmaxf(fmaxf(u0, u1), fmaxf(u2, u3)),
                         fmaxf(fmaxf(u4, u5), fmaxf(u6, u7)));
        float mn = fminf(fminf(fminf(mc[0], mc[1]), fminf(mc[2], mc[3])),
                         fminf(fminf(mc[4], mc[5]), fminf(mc[6], mc[7])));
        if (ug > mn - SKIP_BITS) {
            ms_upd(mc[0], sc[0], u0); ms_upd(mc[1], sc[1], u1);
            ms_upd(mc[2], sc[2], u2); ms_upd(mc[3], sc[3], u3);
            ms_upd(mc[4], sc[4], u4); ms_upd(mc[5], sc[5], u5);
            ms_upd(mc[6], sc[6], u6); ms_upd(mc[7], sc[7], u7);
        }
    }
    #pragma unroll
    for (int q = 0; q < 8; q++) partC[c0 + q][segC] = make_float2(mc[q], sc[q]);
    __syncthreads();

    // phase 2: anchored combine of 16 partials (rows: tid<128, cols: tid>=128)
    if (tid < 128) {
        float2 pr[16];
        #pragma unroll
        for (int k = 0; k < 16; k++) pr[k] = partR[tid][k];
        float M = pr[0].x;
        #pragma unroll
        for (int k = 1; k < 16; k++) M = fmaxf(M, pr[k].x);
        float S = 0.0f;
        #pragma unroll
        for (int k = 0; k < 16; k++) S = fmaf(pr[k].y, ex2_fast(pr[k].x - M), S);
        ta.Pr[mat][(size_t)bj * NPTS + i0 + tid] = make_float2(M, S);
    } else if (!diag) {
        int j = tid - 128;
        float2 pc[16];
        #pragma unroll
        for (int k = 0; k < 16; k++) pc[k] = partC[j][k];
        float M = pc[0].x;
        #pragma unroll
        for (int k = 1; k < 16; k++) M = fmaxf(M, pc[k].x);
        float S = 0.0f;
        #pragma unroll
        for (int k = 0; k < 16; k++) S = fmaf(pc[k].y, ex2_fast(pc[k].x - M), S);
        ta.Pc[mat][(size_t)bi * NPTS + j0 + j] = make_float2(M, S);
    }
}

// ---------------------------------------------------------------------------
// Stage 2: combine 64 (anchor,sum) partials per row; write per-block maxima.
// ---------------------------------------------------------------------------
struct S2 {
    const float2* P[4];
    float* g[4];
    int gslot[4];
};

__global__ void __launch_bounds__(128)
stage2_all(S2 s2, float eps, int avg) {
    const int a = blockIdx.y;
    const int r = blockIdx.x * 128 + threadIdx.x;
    const float2* __restrict__ P = s2.P[a];

    float m = -1e30f, s = 0.0f;
    #pragma unroll 4
    for (int c = 0; c < NCHUNK; c++) {
        float2 p = P[(size_t)c * NPTS + r];
        float M = fmaxf(m, p.x);
        s = s * ex2_fast(m - M) + p.y * ex2_fast(p.x - M);
        m = M;
    }
    float val = -eps * LN2_F * (m + lg2_fast(s));
    if (avg) val = 0.5f * (s2.g[a][r] + val);
    s2.g[a][r] = val;

    __shared__ float red[4];
    float v = val;
    #pragma unroll
    for (int o = 16; o > 0; o >>= 1) v = fmaxf(v, __shfl_xor_sync(0xffffffffu, v, o));
    if ((threadIdx.x & 31) == 0) red[threadIdx.x >> 5] = v;
    __syncthreads();
    if (threadIdx.x == 0) {
        float M = fmaxf(fmaxf(red[0], red[1]), fmaxf(red[2], red[3]));
        d_bmax[s2.gslot[a] * 64 + blockIdx.x] = M;
    }
}

// ---------------------------------------------------------------------------
__global__ void final_kernel(const float* __restrict__ fbf, const float* __restrict__ faf,
                             const float* __restrict__ gaf, const float* __restrict__ gbf,
                             float* __restrict__ out) {
    __shared__ float sh[256];
    float s = 0.0f;
    for (int i = threadIdx.x; i < NPTS; i += 256)
        s += (fbf[i] - faf[i]) + (gaf[i] - gbf[i]);
    sh[threadIdx.x] = s;
    __syncthreads();
    #pragma unroll
    for (int o = 128; o > 0; o >>= 1) {
        if (threadIdx.x < o) sh[threadIdx.x] += sh[threadIdx.x + o];
        __syncthreads();
    }
    if (threadIdx.x == 0) out[0] = sh[0] * (1.0f / (float)NPTS);
}

// ---------------------------------------------------------------------------
extern "C" void kernel_launch(void* const* d_in, const int* in_sizes, int n_in,
                              void* d_out, int out_size) {
    (void)in_sizes; (void)n_in; (void)out_size;
    const float* x = (const float*)d_in[0];
    const float* y = (const float*)d_in[1];
    float* out = (float*)d_out;

    unsigned short* cq = nullptr;
    float2* part = nullptr;
    float *vec = nullptr, *tmin = nullptr;
    cudaGetSymbolAddress((void**)&cq,   d_cq);
    cudaGetSymbolAddress((void**)&part, d_part);
    cudaGetSymbolAddress((void**)&vec,  d_vecbuf);
    cudaGetSymbolAddress((void**)&tmin, d_tilemin);

    unsigned short* Cxy = cq;
    unsigned short* Cxx = cq + NN;
    unsigned short* Cyy = cq + 2 * NN;
    float2* Pft = part;
    float2* Pgt = part + (size_t)NCHUNK * NPTS;
    float2* Pfs = part + 2 * (size_t)NCHUNK * NPTS;
    float2* Pgs = part + 3 * (size_t)NCHUNK * NPTS;

    float* hx   = vec + (size_t)V_HX   * NPTS;
    float* hy   = vec + (size_t)V_HY   * NPTS;
    float* zero = vec + (size_t)V_ZERO * NPTS;
    float* faa  = vec + (size_t)V_FAA  * NPTS;
    float* gbb  = vec + (size_t)V_GBB  * NPTS;
    float* gab  = vec + (size_t)V_GAB  * NPTS;
    float* fba  = vec + (size_t)V_FBA  * NPTS;
    float* ft   = vec + (size_t)V_FT   * NPTS;
    float* gt   = vec + (size_t)V_GT   * NPTS;
    float* fs   = vec + (size_t)V_FS   * NPTS;
    float* gs   = vec + (size_t)V_GS   * NPTS;

    static const float EPS[11] = {1024.0f, 256.0f, 64.0f, 16.0f, 4.0f, 1.0f,
                                  0.25f, 0.0625f, 0.015625f, 0.00390625f, 0.0025f};

    prep_kernel<<<2048, 256>>>(x, y, hx, hy);
    gemm_cost_q<<<dim3(64, 64, 3), 256>>>(x, y, hx, hy, cq, tmin);

    // slots: 0=gab, 1=fba, 2=faa, 3=gbb
    TA init_ta, ta;
    init_ta.C[0] = Cxy; init_ta.C[1] = Cxx; init_ta.C[2] = Cyy;
    init_ta.tmin[0] = tmin; init_ta.tmin[1] = tmin + 4096; init_ta.tmin[2] = tmin + 8192;
    init_ta.Pr[0] = Pft; init_ta.Pc[0] = Pgt;
    init_ta.Pr[1] = Pfs; init_ta.Pc[1] = Pfs;
    init_ta.Pr[2] = Pgs; init_ta.Pc[2] = Pgs;
    init_ta.rslot[0] = 0; init_ta.cslot[0] = 1;
    init_ta.rslot[1] = 2; init_ta.cslot[1] = 2;
    init_ta.rslot[2] = 3; init_ta.cslot[2] = 3;
    for (int m = 0; m < 3; m++) { init_ta.gr[m] = zero; init_ta.gc[m] = zero; }
    ta = init_ta;
    ta.gr[0] = gab; ta.gc[0] = fba;
    ta.gr[1] = faa; ta.gc[1] = faa;
    ta.gr[2] = gbb; ta.gc[2] = gbb;

    S2 s2_loop, s2_fin;
    s2_loop.P[0] = Pft; s2_loop.P[1] = Pgt; s2_loop.P[2] = Pfs; s2_loop.P[3] = Pgs;
    s2_loop.g[0] = fba; s2_loop.g[1] = gab; s2_loop.g[2] = faa; s2_loop.g[3] = gbb;
    s2_loop.gslot[0] = 1; s2_loop.gslot[1] = 0; s2_loop.gslot[2] = 2; s2_loop.gslot[3] = 3;
    s2_fin = s2_loop;
    s2_fin.g[0] = ft; s2_fin.g[1] = gt; s2_fin.g[2] = fs; s2_fin.g[3] = gs;

    dim3 s2g(64, 4);

    {   // init round: eps0 = 1024, g = 0 (d_bmax zeroed in prep)
        float e0 = EPS[0], k1 = LOG2E_F / e0, kb = NEG_LOG_N_F * LOG2E_F;
        tile_softmin_A<<<NTILES_ALL, 256>>>(init_ta, k1, kb);
        stage2_all<<<s2g, 128>>>(s2_loop, e0, 0);
    }

    for (int it = 0; it < 11; it++) {
        float e = EPS[it], k1 = LOG2E_F / e, kb = NEG_LOG_N_F * LOG2E_F;
        if (e >= 16.0f) tile_softmin_A<<<NTILES_ALL, 256>>>(ta, k1, kb);
        else            tile_softmin_B<<<NTILES_ALL, 256>>>(ta, k1, kb);
        stage2_all<<<s2g, 128>>>(s2_loop, e, 1);
    }

    {   // final extrapolation at eps = blur^p
        float ef = EPS[10], k1 = LOG2E_F / ef, kb = NEG_LOG_N_F * LOG2E_F;
        tile_softmin_B<<<NTILES_ALL, 256>>>(ta, k1, kb);
        stage2_all<<<s2g, 128>>>(s2_fin, ef, 0);
    }

    final_kernel<<<1, 256>>>(ft, fs, gt, gs, out);
}

// round 7
// speedup vs baseline: 1.9121x; 1.0437x over previous
#include <cuda_runtime.h>
#include <cstddef>

// ---------------------------------------------------------------------------
// Sinkhorn divergence (geomloss p=2, blur=0.05, scaling=0.5, diameter=32)
// N = M = 8192, D = 64.  R7:
// R6 structure (3 stored u16 matrices, fused row+col tile softmin, Mode A/B)
// + stage2 redesigned (4 partials/row, fixed anchor, MLP-16 loads, no serial
// LSE chain) + zero_bmax mini-launch (also aligns ncu window onto the tile
// kernel).
// ---------------------------------------------------------------------------

#define NPTS 8192
#define DIMS 64
#define NN      ((size_t)NPTS * (size_t)NPTS)
#define NCHUNK  64
#define QSCALE  128.0f
#define QINV    (1.0f / 128.0f)
#define NTILES_XY  4096
#define NTILES_SYM 2080
#define NTILES_ALL (NTILES_XY + 2 * NTILES_SYM)

#define LOG2E_F 1.4426950408889634f
#define LN2_F   0.6931471805599453f
#define NEG_LOG_N_F (-9.010913347279288f)   // -ln(8192)
#define SKIP_BITS 30.0f

__device__ __align__(256) unsigned short d_cq[3 * NN];               // 384 MB
__device__ __align__(256) float2 d_part[4 * (size_t)NCHUNK * NPTS];  // 16 MB
__device__ __align__(256) float  d_tilemin[3 * 4096];
__device__ __align__(256) float  d_vecbuf[11 * NPTS];
__device__ __align__(256) float  d_bmax[4 * 256];   // per-stage2-block maxima

#define V_HX 0
#define V_HY 1
#define V_ZERO 2
#define V_FAA 3
#define V_GBB 4
#define V_GAB 5
#define V_FBA 6
#define V_FT 7
#define V_GT 8
#define V_FS 9
#define V_GS 10

__device__ __forceinline__ float ex2_fast(float x) {
    float r; asm("ex2.approx.ftz.f32 %0, %1;" : "=f"(r) : "f"(x)); return r;
}
__device__ __forceinline__ float lg2_fast(float x) {
    float r; asm("lg2.approx.f32 %0, %1;" : "=f"(r) : "f"(x)); return r;
}
__device__ __forceinline__ float dec_lo(unsigned w) {
    return __uint_as_float(__byte_perm(w, 0x4B000000u, 0x7410)) - 8388608.0f;
}
__device__ __forceinline__ float dec_hi(unsigned w) {
    return __uint_as_float(__byte_perm(w, 0x4B000000u, 0x7432)) - 8388608.0f;
}

// ---------------------------------------------------------------------------
__global__ void prep_kernel(const float* __restrict__ x, const float* __restrict__ y,
                            float* __restrict__ hx, float* __restrict__ hy) {
    int gw = (blockIdx.x * blockDim.x + threadIdx.x) >> 5;
    int lane = threadIdx.x & 31;
    const float* X = (gw < NPTS) ? x : y;
    float* H = (gw < NPTS) ? hx : hy;
    int row = (gw < NPTS) ? gw : gw - NPTS;
    float v0 = X[(size_t)row * DIMS + lane];
    float v1 = X[(size_t)row * DIMS + 32 + lane];
    float s = v0 * v0 + v1 * v1;
    #pragma unroll
    for (int o = 16; o > 0; o >>= 1) s += __shfl_xor_sync(0xffffffffu, s, o);
    if (lane == 0) H[row] = 0.5f * s;
}

__global__ void zero_bmax_kernel() {
    d_bmax[blockIdx.x * 256 + threadIdx.x] = 0.0f;
}

// ---------------------------------------------------------------------------
// merged GEMM: z=0 Cxy(x,y), z=1 Cxx(x,x) upper, z=2 Cyy(y,y) upper.
// ---------------------------------------------------------------------------
__global__ void __launch_bounds__(256)
gemm_cost_q(const float* __restrict__ x, const float* __restrict__ y,
            const float* __restrict__ hx, const float* __restrict__ hy,
            unsigned short* __restrict__ cq, float* __restrict__ tmin) {
    const int mz = blockIdx.z;
    int bi = blockIdx.y, bj = blockIdx.x;
    if (mz > 0 && bi > bj) return;
    const float* A  = (mz == 2) ? y : x;
    const float* B  = (mz == 0 || mz == 2) ? y : x;
    const float* ha = (mz == 2) ? hy : hx;
    const float* hb = (mz == 0 || mz == 2) ? hy : hx;
    unsigned short* C = cq + (size_t)mz * NN;
    float* tileminf = tmin + mz * 4096;

    const int i0 = bi * 128, j0 = bj * 128;
    __shared__ float As[32][132];
    __shared__ float Bs[32][132];
    __shared__ unsigned sm_min[8];

    const int tid = threadIdx.x;
    const int lane = tid & 31, warp = tid >> 5;
    const int wy = warp >> 1, wx = warp & 1;
    const int ty2 = lane & 3, tx2 = lane >> 2;
    const int r0 = wy * 32 + ty2 * 8;
    const int c0 = wx * 64 + tx2 * 8;

    float acc[8][8];
    #pragma unroll
    for (int p = 0; p < 8; p++)
        #pragma unroll
        for (int q = 0; q < 8; q++) acc[p][q] = 0.0f;

    #pragma unroll
    for (int kc = 0; kc < 2; kc++) {
        #pragma unroll
        for (int u = 0; u < 4; u++) {
            int idx = tid + 256 * u;
            int row = idx >> 3, kq = idx & 7;
            float4 av = *(const float4*)(A + (size_t)(i0 + row) * DIMS + kc * 32 + kq * 4);
            float4 bv = *(const float4*)(B + (size_t)(j0 + row) * DIMS + kc * 32 + kq * 4);
            As[kq * 4 + 0][row] = av.x; As[kq * 4 + 1][row] = av.y;
            As[kq * 4 + 2][row] = av.z; As[kq * 4 + 3][row] = av.w;
            Bs[kq * 4 + 0][row] = bv.x; Bs[kq * 4 + 1][row] = bv.y;
            Bs[kq * 4 + 2][row] = bv.z; Bs[kq * 4 + 3][row] = bv.w;
        }
        __syncthreads();
        #pragma unroll 4
        for (int k = 0; k < 32; k++) {
            float a[8], b[8];
            *(float4*)&a[0] = *(const float4*)&As[k][r0];
            *(float4*)&a[4] = *(const float4*)&As[k][r0 + 4];
            *(float4*)&b[0] = *(const float4*)&Bs[k][c0];
            *(float4*)&b[4] = *(const float4*)&Bs[k][c0 + 4];
            #pragma unroll
            for (int p = 0; p < 8; p++)
                #pragma unroll
                for (int q = 0; q < 8; q++)
                    acc[p][q] = fmaf(a[p], b[q], acc[p][q]);
        }
        __syncthreads();
    }

    float hav[8], hbv[8];
    #pragma unroll
    for (int p = 0; p < 8; p++) hav[p] = ha[i0 + r0 + p];
    #pragma unroll
    for (int q = 0; q < 8; q++) hbv[q] = hb[j0 + c0 + q];

    unsigned tvmin = 0xFFFFu;
    #pragma unroll
    for (int p = 0; p < 8; p++) {
        unsigned v[8];
        #pragma unroll
        for (int q = 0; q < 8; q++) {
            float val = fmaxf(hav[p] + hbv[q] - acc[p][q], 0.0f) * QSCALE;
            unsigned xq = __float2uint_rn(val);
            v[q] = xq > 65535u ? 65535u : xq;
            tvmin = min(tvmin, v[q]);
        }
        uint4 w;
        w.x = v[0] | (v[1] << 16); w.y = v[2] | (v[3] << 16);
        w.z = v[4] | (v[5] << 16); w.w = v[6] | (v[7] << 16);
        *(uint4*)(C + (size_t)(i0 + r0 + p) * NPTS + j0 + c0) = w;
    }
    #pragma unroll
    for (int o = 16; o > 0; o >>= 1)
        tvmin = min(tvmin, __shfl_xor_sync(0xffffffffu, tvmin, o));
    if (lane == 0) sm_min[warp] = tvmin;
    __syncthreads();
    if (tid == 0) {
        unsigned mn = sm_min[0];
        #pragma unroll
        for (int i = 1; i < 8; i++) mn = min(mn, sm_min[i]);
        tileminf[bi * 64 + bj] = (float)mn;
    }
}

// ---------------------------------------------------------------------------
__device__ __forceinline__ void decode_tile(int xx, int& mat, int& bi, int& bj, bool& diag) {
    if (xx < NTILES_XY) { mat = 0; bi = xx >> 6; bj = xx & 63; diag = false; return; }
    int idx = xx - NTILES_XY; mat = 1;
    if (idx >= NTILES_SYM) { idx -= NTILES_SYM; mat = 2; }
    int b = 0;
    while (idx >= 64 - b) { idx -= 64 - b; b++; }
    bi = b; bj = b + idx; diag = (bi == bj);
}

struct TA {
    const unsigned short* C[3];
    const float* tmin[3];
    const float* gr[3];
    const float* gc[3];
    float2* Pr[3];
    float2* Pc[3];
    int rslot[3], cslot[3];
};

// ---------------------------------------------------------------------------
// Mode A (eps >= 16): factored exponential, per-tile anchor, 1 ex2/element.
// ---------------------------------------------------------------------------
__global__ void __launch_bounds__(256)
tile_softmin_A(TA ta, float k1, float kb) {
    int mat, bi, bj; bool diag;
    decode_tile(blockIdx.x, mat, bi, bj, diag);
    const int i0 = bi * 128, j0 = bj * 128;
    const unsigned short* __restrict__ C = ta.C[mat];

    __shared__ float Rj[128], Si[128];
    __shared__ float s_gm[2];
    __shared__ float partR[128][17];
    __shared__ float partC[128][17];

    const int tid = threadIdx.x;
    const int lane = tid & 31, warp = tid >> 5;
    const int wy = warp >> 1, wx = warp & 1;
    const int ty2 = lane & 3, tx2 = lane >> 2;
    const int r0 = wy * 32 + ty2 * 8;
    const int c0 = wx * 64 + tx2 * 8;
    const int segR = wx * 8 + tx2;
    const int segC = wy * 4 + ty2;

    if (warp < 2) {
        int slot = (warp == 0) ? ta.rslot[mat] : ta.cslot[mat];
        float v = d_bmax[slot * 256 + lane];
        #pragma unroll
        for (int k = 1; k < 8; k++)
            v = fmaxf(v, d_bmax[slot * 256 + lane + 32 * k]);
        #pragma unroll
        for (int o = 16; o > 0; o >>= 1) v = fmaxf(v, __shfl_xor_sync(0xffffffffu, v, o));
        if (lane == 0) s_gm[warp] = v;
    }
    __syncthreads();
    const float gmr = s_gm[0], gmc = s_gm[1];
    const float tminq = ta.tmin[mat][bi * 64 + bj];

    if (tid < 128) {
        Rj[tid] = ex2_fast((ta.gr[mat][j0 + tid] - gmr) * k1);
        Si[tid] = ex2_fast((ta.gc[mat][i0 + tid] - gmc) * k1);
    }
    __syncthreads();

    uint4 w[8];
    #pragma unroll
    for (int p = 0; p < 8; p++)
        w[p] = *(const uint4*)(C + (size_t)(i0 + r0 + p) * NPTS + j0 + c0);

    const float kq  = -k1 * QINV;
    const float c0f = -tminq * kq;

    float rj[8];
    #pragma unroll
    for (int q = 0; q < 8; q++) rj[q] = Rj[c0 + q];
    float cs[8];
    #pragma unroll
    for (int q = 0; q < 8; q++) cs[q] = 0.0f;

    #pragma unroll
    for (int p = 0; p < 8; p++) {
        float sp = Si[r0 + p];
        uint4 wq = w[p];
        float e0 = ex2_fast(fmaf(dec_lo(wq.x), kq, c0f));
        float e1 = ex2_fast(fmaf(dec_hi(wq.x), kq, c0f));
        float e2 = ex2_fast(fmaf(dec_lo(wq.y), kq, c0f));
        float e3 = ex2_fast(fmaf(dec_hi(wq.y), kq, c0f));
        float e4 = ex2_fast(fmaf(dec_lo(wq.z), kq, c0f));
        float e5 = ex2_fast(fmaf(dec_hi(wq.z), kq, c0f));
        float e6 = ex2_fast(fmaf(dec_lo(wq.w), kq, c0f));
        float e7 = ex2_fast(fmaf(dec_hi(wq.w), kq, c0f));
        partR[r0 + p][segR] = e0 * rj[0] + e1 * rj[1] + e2 * rj[2] + e3 * rj[3]
                            + e4 * rj[4] + e5 * rj[5] + e6 * rj[6] + e7 * rj[7];
        cs[0] = fmaf(e0, sp, cs[0]); cs[1] = fmaf(e1, sp, cs[1]);
        cs[2] = fmaf(e2, sp, cs[2]); cs[3] = fmaf(e3, sp, cs[3]);
        cs[4] = fmaf(e4, sp, cs[4]); cs[5] = fmaf(e5, sp, cs[5]);
        cs[6] = fmaf(e6, sp, cs[6]); cs[7] = fmaf(e7, sp, cs[7]);
    }
    #pragma unroll
    for (int q = 0; q < 8; q++) partC[c0 + q][segC] = cs[q];
    __syncthreads();

    const float A_r = fmaf(k1, gmr, kb) + kq * tminq;
    const float A_c = fmaf(k1, gmc, kb) + kq * tminq;
    if (tid < 128) {
        float s = 0.0f;
        #pragma unroll
        for (int k = 0; k < 16; k++) s += partR[tid][k];
        ta.Pr[mat][(size_t)bj * NPTS + i0 + tid] = make_float2(A_r, s);
    } else if (!diag) {
        int j = tid - 128;
        float s = 0.0f;
        #pragma unroll
        for (int k = 0; k < 16; k++) s += partC[j][k];
        ta.Pc[mat][(size_t)bi * NPTS + j0 + j] = make_float2(A_c, s);
    }
}

// ---------------------------------------------------------------------------
// Mode B (eps < 16): anchored group partials + 30-bit col skip.
// ---------------------------------------------------------------------------
__device__ __forceinline__ void ms_upd(float& mq, float& sq, float t) {
    if (t > mq) { sq = fmaf(sq, ex2_fast(mq - t), 1.0f); mq = t; }
    else        { sq += ex2_fast(t - mq); }
}

__global__ void __launch_bounds__(256)
tile_softmin_B(TA ta, float k1, float kb) {
    int mat, bi, bj; bool diag;
    decode_tile(blockIdx.x, mat, bi, bj, diag);
    const int i0 = bi * 128, j0 = bj * 128;
    const unsigned short* __restrict__ C = ta.C[mat];

    __shared__ float Gr[128], Gc[128];
    __shared__ float2 partR[128][17];
    __shared__ float2 partC[128][17];

    const int tid = threadIdx.x;
    const int lane = tid & 31, warp = tid >> 5;
    const int wy = warp >> 1, wx = warp & 1;
    const int ty2 = lane & 3, tx2 = lane >> 2;
    const int r0 = wy * 32 + ty2 * 8;
    const int c0 = wx * 64 + tx2 * 8;
    const int segR = wx * 8 + tx2;
    const int segC = wy * 4 + ty2;

    if (tid < 128) {
        Gr[tid] = fmaf(ta.gr[mat][j0 + tid], k1, kb);
        Gc[tid] = fmaf(ta.gc[mat][i0 + tid], k1, kb);
    }
    __syncthreads();

    uint4 w[8];
    #pragma unroll
    for (int p = 0; p < 8; p++)
        w[p] = *(const uint4*)(C + (size_t)(i0 + r0 + p) * NPTS + j0 + c0);

    const float kq = -k1 * QINV;
    float G[8];
    #pragma unroll
    for (int q = 0; q < 8; q++) G[q] = Gr[c0 + q];

    float mc[8], sc[8];
    #pragma unroll
    for (int q = 0; q < 8; q++) { mc[q] = -1e30f; sc[q] = 0.0f; }

    #pragma unroll
    for (int p = 0; p < 8; p++) {
        uint4 wq = w[p];
        float d0 = dec_lo(wq.x), d1 = dec_hi(wq.x);
        float d2 = dec_lo(wq.y), d3 = dec_hi(wq.y);
        float d4 = dec_lo(wq.z), d5 = dec_hi(wq.z);
        float d6 = dec_lo(wq.w), d7 = dec_hi(wq.w);

        float t0 = fmaf(d0, kq, G[0]), t1 = fmaf(d1, kq, G[1]);
        float t2 = fmaf(d2, kq, G[2]), t3 = fmaf(d3, kq, G[3]);
        float t4 = fmaf(d4, kq, G[4]), t5 = fmaf(d5, kq, G[5]);
        float t6 = fmaf(d6, kq, G[6]), t7 = fmaf(d7, kq, G[7]);
        float mp = fmaxf(fmaxf(fmaxf(t0, t1), fmaxf(t2, t3)),
                         fmaxf(fmaxf(t4, t5), fmaxf(t6, t7)));
        float sp = ex2_fast(t0 - mp) + ex2_fast(t1 - mp)
                 + ex2_fast(t2 - mp) + ex2_fast(t3 - mp)
                 + ex2_fast(t4 - mp) + ex2_fast(t5 - mp)
                 + ex2_fast(t6 - mp) + ex2_fast(t7 - mp);
        partR[r0 + p][segR] = make_float2(mp, sp);

        float gcp = Gc[r0 + p];
        float u0 = fmaf(d0, kq, gcp), u1 = fmaf(d1, kq, gcp);
        float u2 = fmaf(d2, kq, gcp), u3 = fmaf(d3, kq, gcp);
        float u4 = fmaf(d4, kq, gcp), u5 = fmaf(d5, kq, gcp);
        float u6 = fmaf(d6, kq, gcp), u7 = fmaf(d7, kq, gcp);
        float ug = fmaxf(fmaxf(fmaxf(u0, u1), fmaxf(u2, u3)),
                         fmaxf(fmaxf(u4, u5), fmaxf(u6, u7)));
        float mn = fminf(fminf(fminf(mc[0], mc[1]), fminf(mc[2], mc[3])),
                         fminf(fminf(mc[4], mc[5]), fminf(mc[6], mc[7])));
        if (ug > mn - SKIP_BITS) {
            ms_upd(mc[0], sc[0], u0); ms_upd(mc[1], sc[1], u1);
            ms_upd(mc[2], sc[2], u2); ms_upd(mc[3], sc[3], u3);
            ms_upd(mc[4], sc[4], u4); ms_upd(mc[5], sc[5], u5);
            ms_upd(mc[6], sc[6], u6); ms_upd(mc[7], sc[7], u7);
        }
    }
    #pragma unroll
    for (int q = 0; q < 8; q++) partC[c0 + q][segC] = make_float2(mc[q], sc[q]);
    __syncthreads();

    if (tid < 128) {
        float2 pr[16];
        #pragma unroll
        for (int k = 0; k < 16; k++) pr[k] = partR[tid][k];
        float M = pr[0].x;
        #pragma unroll
        for (int k = 1; k < 16; k++) M = fmaxf(M, pr[k].x);
        float S = 0.0f;
        #pragma unroll
        for (int k = 0; k < 16; k++) S = fmaf(pr[k].y, ex2_fast(pr[k].x - M), S);
        ta.Pr[mat][(size_t)bj * NPTS + i0 + tid] = make_float2(M, S);
    } else if (!diag) {
        int j = tid - 128;
        float2 pc[16];
        #pragma unroll
        for (int k = 0; k < 16; k++) pc[k] = partC[j][k];
        float M = pc[0].x;
        #pragma unroll
        for (int k = 1; k < 16; k++) M = fmaxf(M, pc[k].x);
        float S = 0.0f;
        #pragma unroll
        for (int k = 0; k < 16; k++) S = fmaf(pc[k].y, ex2_fast(pc[k].x - M), S);
        ta.Pc[mat][(size_t)bi * NPTS + j0 + j] = make_float2(M, S);
    }
}

// ---------------------------------------------------------------------------
// Stage 2: 4 partials per row (warp = one 16-chunk slice of 32 rows),
// fixed-anchor combine; no serial LSE chain; MLP-16 loads.
// grid (256, 4), 128 threads.
// ---------------------------------------------------------------------------
struct S2 {
    const float2* P[4];
    float* g[4];
    int gslot[4];
};

__global__ void __launch_bounds__(128)
stage2_all(S2 s2, float eps, int avg) {
    const int a = blockIdx.y;
    const int lane = threadIdx.x & 31;
    const int part = threadIdx.x >> 5;          // 0..3 (16 chunks each)
    const int r = blockIdx.x * 32 + lane;
    const float2* __restrict__ P = s2.P[a] + (size_t)part * 16 * NPTS + r;

    float2 p[16];
    #pragma unroll
    for (int k = 0; k < 16; k++) p[k] = P[(size_t)k * NPTS];
    float M = p[0].x;
    #pragma unroll
    for (int k = 1; k < 16; k++) M = fmaxf(M, p[k].x);
    float S = 0.0f;
    #pragma unroll
    for (int k = 0; k < 16; k++) S = fmaf(p[k].y, ex2_fast(p[k].x - M), S);

    __shared__ float sm_m[4][33], sm_s[4][33];
    sm_m[part][lane] = M;
    sm_s[part][lane] = S;
    __syncthreads();

    if (threadIdx.x < 32) {
        float m0 = sm_m[0][lane], m1 = sm_m[1][lane];
        float m2 = sm_m[2][lane], m3 = sm_m[3][lane];
        float Mx = fmaxf(fmaxf(m0, m1), fmaxf(m2, m3));
        float Sx = sm_s[0][lane] * ex2_fast(m0 - Mx)
                 + sm_s[1][lane] * ex2_fast(m1 - Mx)
                 + sm_s[2][lane] * ex2_fast(m2 - Mx)
                 + sm_s[3][lane] * ex2_fast(m3 - Mx);
        float val = -eps * LN2_F * (Mx + lg2_fast(Sx));
        if (avg) val = 0.5f * (s2.g[a][r] + val);
        s2.g[a][r] = val;

        float v = val;
        #pragma unroll
        for (int o = 16; o > 0; o >>= 1) v = fmaxf(v, __shfl_xor_sync(0xffffffffu, v, o));
        if (lane == 0) d_bmax[s2.gslot[a] * 256 + blockIdx.x] = v;
    }
}

// ---------------------------------------------------------------------------
__global__ void final_kernel(const float* __restrict__ fbf, const float* __restrict__ faf,
                             const float* __restrict__ gaf, const float* __restrict__ gbf,
                             float* __restrict__ out) {
    __shared__ float sh[256];
    float s = 0.0f;
    for (int i = threadIdx.x; i < NPTS; i += 256)
        s += (fbf[i] - faf[i]) + (gaf[i] - gbf[i]);
    sh[threadIdx.x] = s;
    __syncthreads();
    #pragma unroll
    for (int o = 128; o > 0; o >>= 1) {
        if (threadIdx.x < o) sh[threadIdx.x] += sh[threadIdx.x + o];
        __syncthreads();
    }
    if (threadIdx.x == 0) out[0] = sh[0] * (1.0f / (float)NPTS);
}

// ---------------------------------------------------------------------------
extern "C" void kernel_launch(void* const* d_in, const int* in_sizes, int n_in,
                              void* d_out, int out_size) {
    (void)in_sizes; (void)n_in; (void)out_size;
    const float* x = (const float*)d_in[0];
    const float* y = (const float*)d_in[1];
    float* out = (float*)d_out;

    unsigned short* cq = nullptr;
    float2* part = nullptr;
    float *vec = nullptr, *tmin = nullptr;
    cudaGetSymbolAddress((void**)&cq,   d_cq);
    cudaGetSymbolAddress((void**)&part, d_part);
    cudaGetSymbolAddress((void**)&vec,  d_vecbuf);
    cudaGetSymbolAddress((void**)&tmin, d_tilemin);

    unsigned short* Cxy = cq;
    unsigned short* Cxx = cq + NN;
    unsigned short* Cyy = cq + 2 * NN;
    float2* Pft = part;
    float2* Pgt = part + (size_t)NCHUNK * NPTS;
    float2* Pfs = part + 2 * (size_t)NCHUNK * NPTS;
    float2* Pgs = part + 3 * (size_t)NCHUNK * NPTS;

    float* hx   = vec + (size_t)V_HX   * NPTS;
    float* hy   = vec + (size_t)V_HY   * NPTS;
    float* zero = vec + (size_t)V_ZERO * NPTS;
    float* faa  = vec + (size_t)V_FAA  * NPTS;
    float* gbb  = vec + (size_t)V_GBB  * NPTS;
    float* gab  = vec + (size_t)V_GAB  * NPTS;
    float* fba  = vec + (size_t)V_FBA  * NPTS;
    float* ft   = vec + (size_t)V_FT   * NPTS;
    float* gt   = vec + (size_t)V_GT   * NPTS;
    float* fs   = vec + (size_t)V_FS   * NPTS;
    float* gs   = vec + (size_t)V_GS   * NPTS;

    static const float EPS[11] = {1024.0f, 256.0f, 64.0f, 16.0f, 4.0f, 1.0f,
                                  0.25f, 0.0625f, 0.015625f, 0.00390625f, 0.0025f};

    prep_kernel<<<2048, 256>>>(x, y, hx, hy);
    zero_bmax_kernel<<<4, 256>>>();
    gemm_cost_q<<<dim3(64, 64, 3), 256>>>(x, y, hx, hy, cq, tmin);

    TA init_ta, ta;
    init_ta.C[0] = Cxy; init_ta.C[1] = Cxx; init_ta.C[2] = Cyy;
    init_ta.tmin[0] = tmin; init_ta.tmin[1] = tmin + 4096; init_ta.tmin[2] = tmin + 8192;
    init_ta.Pr[0] = Pft; init_ta.Pc[0] = Pgt;
    init_ta.Pr[1] = Pfs; init_ta.Pc[1] = Pfs;
    init_ta.Pr[2] = Pgs; init_ta.Pc[2] = Pgs;
    init_ta.rslot[0] = 0; init_ta.cslot[0] = 1;
    init_ta.rslot[1] = 2; init_ta.cslot[1] = 2;
    init_ta.rslot[2] = 3; init_ta.cslot[2] = 3;
    for (int m = 0; m < 3; m++) { init_ta.gr[m] = zero; init_ta.gc[m] = zero; }
    ta = init_ta;
    ta.gr[0] = gab; ta.gc[0] = fba;
    ta.gr[1] = faa; ta.gc[1] = faa;
    ta.gr[2] = gbb; ta.gc[2] = gbb;

    S2 s2_loop, s2_fin;
    s2_loop.P[0] = Pft; s2_loop.P[1] = Pgt; s2_loop.P[2] = Pfs; s2_loop.P[3] = Pgs;
    s2_loop.g[0] = fba; s2_loop.g[1] = gab; s2_loop.g[2] = faa; s2_loop.g[3] = gbb;
    s2_loop.gslot[0] = 1; s2_loop.gslot[1] = 0; s2_loop.gslot[2] = 2; s2_loop.gslot[3] = 3;
    s2_fin = s2_loop;
    s2_fin.g[0] = ft; s2_fin.g[1] = gt; s2_fin.g[2] = fs; s2_fin.g[3] = gs;

    dim3 s2g(256, 4);

    {   // init round: eps0 = 1024, g = 0 (d_bmax zeroed above)
        float e0 = EPS[0], k1 = LOG2E_F / e0, kb = NEG_LOG_N_F * LOG2E_F;
        tile_softmin_A<<<NTILES_ALL, 256>>>(init_ta, k1, kb);
        stage2_all<<<s2g, 128>>>(s2_loop, e0, 0);
    }

    for (int it = 0; it < 11; it++) {
        float e = EPS[it], k1 = LOG2E_F / e, kb = NEG_LOG_N_F * LOG2E_F;
        if (e >= 16.0f) tile_softmin_A<<<NTILES_ALL, 256>>>(ta, k1, kb);
        else            tile_softmin_B<<<NTILES_ALL, 256>>>(ta, k1, kb);
        stage2_all<<<s2g, 128>>>(s2_loop, e, 1);
    }

    {   // final extrapolation at eps = blur^p
        float ef = EPS[10], k1 = LOG2E_F / ef, kb = NEG_LOG_N_F * LOG2E_F;
        tile_softmin_B<<<NTILES_ALL, 256>>>(ta, k1, kb);
        stage2_all<<<s2g, 128>>>(s2_fin, ef, 0);
    }

    final_kernel<<<1, 256>>>(ft, fs, gt, gs, out);
}